// round 1
// baseline (speedup 1.0000x reference)
#include <cuda_runtime.h>
#include <math.h>

// ---------------------------------------------------------------------------
// Problem constants (Self_Attention_8340826489591)
// N=4096 tokens, D=4096 model dim, H=8 heads, DH=512 head dim
// ---------------------------------------------------------------------------
#define NTOK 4096
#define DMODEL 4096
#define NHEADS 8
#define DHEAD 512
#define ATTN_SCALE 0.04419417382415922f  // 1/sqrt(512)

// Static device scratch (allocation-free rule: __device__ globals)
__device__ float g_Q[(size_t)NTOK * DMODEL];
__device__ float g_K[(size_t)NTOK * DMODEL];
__device__ float g_V[(size_t)NTOK * DMODEL];
__device__ float g_R1[(size_t)NTOK * DMODEL];
__device__ int g_seg_start[NTOK];
__device__ int g_seg_end[NTOK];

// ---------------------------------------------------------------------------
// Segment table builder.
// num_rels may arrive as int32 (JAX default) or int64 (x64 enabled).
// Detect: if sum of first `count` int32 words != NTOK, interpret as int64
// (values < 2^31, little-endian -> value i at word 2*i, high word 0).
// ---------------------------------------------------------------------------
__global__ void build_seg_kernel(const int* __restrict__ nr, int count) {
    __shared__ int starts[160];
    __shared__ int nseg;
    if (count > 128) count = 128;
    if (threadIdx.x == 0) {
        long long s32 = 0;
        for (int i = 0; i < count; i++) s32 += nr[i];
        int is64 = (s32 != (long long)NTOK) ? 1 : 0;
        int acc = 0;
        for (int i = 0; i < count; i++) {
            starts[i] = acc;
            int v = is64 ? nr[2 * i] : nr[i];
            acc += v;
        }
        starts[count] = acc;
        nseg = count;
    }
    __syncthreads();
    int ns = nseg;
    for (int t = threadIdx.x; t < NTOK; t += blockDim.x) {
        // linear scan over <=128 segments (zero-length segments skip naturally)
        int lo = 0;
        while (lo + 1 <= ns && starts[lo + 1] <= t) lo++;
        g_seg_start[t] = starts[lo];
        g_seg_end[t] = starts[lo + 1];
    }
}

// ---------------------------------------------------------------------------
// Tiled SGEMM: C[M,N] = A[M,K] @ B[K,N] + bias[N] (+ res[M,N] if res != null)
// BM=BN=128, BK=8, 256 threads, 8x8 register tile per thread.
// M,N,K all multiples of 128 here (4096).
// ---------------------------------------------------------------------------
#define BM 128
#define BN 128
#define BK 8
#define TM 8
#define TN 8

__global__ __launch_bounds__(256)
void sgemm_bias_res(const float* __restrict__ A, const float* __restrict__ B,
                    const float* __restrict__ bias, const float* __restrict__ res,
                    float* __restrict__ C, int M, int N, int K) {
    __shared__ float As[BK][BM];      // transposed A tile
    __shared__ float Bs[BK][BN];

    const int tid = threadIdx.x;
    const int brow = blockIdx.y;      // row tile
    const int bcol = blockIdx.x;      // col tile

    const int trow = tid / 16;        // 0..15
    const int tcol = tid % 16;        // 0..15

    // A tile load mapping: 128 rows x 8 cols, one float4 per thread
    const int aRow = tid >> 1;              // 0..127
    const int aCol = (tid & 1) * 4;         // 0 or 4
    // B tile load mapping: 8 rows x 128 cols, one float4 per thread
    const int bRow = tid >> 5;              // 0..7
    const int bCol = (tid & 31) * 4;        // 0..124

    const float* Ab = A + (size_t)brow * BM * K;
    const float* Bb = B + (size_t)bcol * BN;

    float acc[TM][TN];
#pragma unroll
    for (int m = 0; m < TM; m++)
#pragma unroll
        for (int n = 0; n < TN; n++) acc[m][n] = 0.0f;

    for (int k0 = 0; k0 < K; k0 += BK) {
        float4 a4 = *reinterpret_cast<const float4*>(Ab + (size_t)aRow * K + k0 + aCol);
        As[aCol + 0][aRow] = a4.x;
        As[aCol + 1][aRow] = a4.y;
        As[aCol + 2][aRow] = a4.z;
        As[aCol + 3][aRow] = a4.w;
        float4 b4 = *reinterpret_cast<const float4*>(Bb + (size_t)(k0 + bRow) * N + bCol);
        *reinterpret_cast<float4*>(&Bs[bRow][bCol]) = b4;
        __syncthreads();

#pragma unroll
        for (int kk = 0; kk < BK; kk++) {
            float ar[TM], br[TN];
            float4 a0 = *reinterpret_cast<const float4*>(&As[kk][trow * TM]);
            float4 a1 = *reinterpret_cast<const float4*>(&As[kk][trow * TM + 4]);
            ar[0] = a0.x; ar[1] = a0.y; ar[2] = a0.z; ar[3] = a0.w;
            ar[4] = a1.x; ar[5] = a1.y; ar[6] = a1.z; ar[7] = a1.w;
            float4 b0 = *reinterpret_cast<const float4*>(&Bs[kk][tcol * TN]);
            float4 b1 = *reinterpret_cast<const float4*>(&Bs[kk][tcol * TN + 4]);
            br[0] = b0.x; br[1] = b0.y; br[2] = b0.z; br[3] = b0.w;
            br[4] = b1.x; br[5] = b1.y; br[6] = b1.z; br[7] = b1.w;
#pragma unroll
            for (int m = 0; m < TM; m++)
#pragma unroll
                for (int n = 0; n < TN; n++)
                    acc[m][n] = fmaf(ar[m], br[n], acc[m][n]);
        }
        __syncthreads();
    }

    // epilogue: + bias (+ residual)
    const int rowBase = brow * BM + trow * TM;
    const int colBase = bcol * BN + tcol * TN;
#pragma unroll
    for (int m = 0; m < TM; m++) {
        const int row = rowBase + m;
        float* Cr = C + (size_t)row * N + colBase;
#pragma unroll
        for (int n = 0; n < TN; n += 4) {
            float4 v;
            v.x = acc[m][n + 0] + bias[colBase + n + 0];
            v.y = acc[m][n + 1] + bias[colBase + n + 1];
            v.z = acc[m][n + 2] + bias[colBase + n + 2];
            v.w = acc[m][n + 3] + bias[colBase + n + 3];
            if (res != nullptr) {
                const float4 r = *reinterpret_cast<const float4*>(res + (size_t)row * N + colBase + n);
                v.x += r.x; v.y += r.y; v.z += r.z; v.w += r.w;
            }
            *reinterpret_cast<float4*>(Cr + n) = v;
        }
    }
}

// ---------------------------------------------------------------------------
// Block-diagonal attention, flash-style online softmax.
// One warp per (query token, head). 256 threads = 8 queries per block.
// R1[q, h*DH + d] = context + X residual.
// ---------------------------------------------------------------------------
__global__ __launch_bounds__(256)
void attn_kernel(const float* __restrict__ Q, const float* __restrict__ K,
                 const float* __restrict__ V, const float* __restrict__ X,
                 float* __restrict__ R1) {
    const int lane = threadIdx.x & 31;
    const int warp = threadIdx.x >> 5;
    const int q = blockIdx.x * 8 + warp;
    const int h = blockIdx.y;
    if (q >= NTOK) return;

    const int s0 = g_seg_start[q];
    const int s1 = g_seg_end[q];

    const size_t hoff = (size_t)h * DHEAD;
    const float* qrow = Q + (size_t)q * DMODEL + hoff;

    // 16 elements per lane, strided by 32 for coalescing
    float qreg[16];
#pragma unroll
    for (int i = 0; i < 16; i++) qreg[i] = qrow[lane + 32 * i];

    float m = -1e30f;
    float l = 0.0f;
    float accv[16];
#pragma unroll
    for (int i = 0; i < 16; i++) accv[i] = 0.0f;

    for (int j = s0; j < s1; j++) {
        const float* krow = K + (size_t)j * DMODEL + hoff;
        float s = 0.0f;
#pragma unroll
        for (int i = 0; i < 16; i++) s = fmaf(qreg[i], krow[lane + 32 * i], s);
        // warp sum
#pragma unroll
        for (int off = 16; off > 0; off >>= 1)
            s += __shfl_xor_sync(0xFFFFFFFFu, s, off);
        s *= ATTN_SCALE;

        const float mn = fmaxf(m, s);
        const float c = __expf(m - mn);
        const float p = __expf(s - mn);
        l = l * c + p;
        const float* vrow = V + (size_t)j * DMODEL + hoff;
#pragma unroll
        for (int i = 0; i < 16; i++)
            accv[i] = fmaf(accv[i], c, p * vrow[lane + 32 * i]);
        m = mn;
    }

    const float inv = 1.0f / l;
    const float* xr = X + (size_t)q * DMODEL + hoff;
    float* orow = R1 + (size_t)q * DMODEL + hoff;
#pragma unroll
    for (int i = 0; i < 16; i++)
        orow[lane + 32 * i] = accv[i] * inv + xr[lane + 32 * i];
}

// ---------------------------------------------------------------------------
// kernel_launch
// inputs: prod_rep, num_rels, Wq, bq, Wk, bk, Wv, bv, Wfc, bfc
// ---------------------------------------------------------------------------
extern "C" void kernel_launch(void* const* d_in, const int* in_sizes, int n_in,
                              void* d_out, int out_size) {
    const float* X   = (const float*)d_in[0];
    const int*   nr  = (const int*)d_in[1];
    const float* Wq  = (const float*)d_in[2];
    const float* bq  = (const float*)d_in[3];
    const float* Wk  = (const float*)d_in[4];
    const float* bk  = (const float*)d_in[5];
    const float* Wv  = (const float*)d_in[6];
    const float* bv  = (const float*)d_in[7];
    const float* Wfc = (const float*)d_in[8];
    const float* bfc = (const float*)d_in[9];
    float* out = (float*)d_out;

    float *Q, *K, *V, *R1;
    cudaGetSymbolAddress((void**)&Q,  g_Q);
    cudaGetSymbolAddress((void**)&K,  g_K);
    cudaGetSymbolAddress((void**)&V,  g_V);
    cudaGetSymbolAddress((void**)&R1, g_R1);

    const int M = NTOK, N = DMODEL, Kd = DMODEL;

    // 1) segment table
    build_seg_kernel<<<1, 256>>>(nr, in_sizes[1]);

    // 2) Q/K/V projections
    dim3 ggrid(N / BN, M / BM);
    sgemm_bias_res<<<ggrid, 256>>>(X, Wq, bq, nullptr, Q, M, N, Kd);
    sgemm_bias_res<<<ggrid, 256>>>(X, Wk, bk, nullptr, K, M, N, Kd);
    sgemm_bias_res<<<ggrid, 256>>>(X, Wv, bv, nullptr, V, M, N, Kd);

    // 3) block-diagonal attention + residual -> R1
    dim3 agrid(NTOK / 8, NHEADS);
    attn_kernel<<<agrid, 256>>>(Q, K, V, X, R1);

    // 4) res2 = R1 + R1 @ Wfc + bfc -> out
    sgemm_bias_res<<<ggrid, 256>>>(R1, Wfc, bfc, R1, out, M, N, Kd);
}

// round 3
// speedup vs baseline: 2.3185x; 2.3185x over previous
#include <cuda_runtime.h>
#include <cuda_bf16.h>
#include <math.h>
#include <stdint.h>

// ---------------------------------------------------------------------------
// Self_Attention: N=4096 tokens, D=4096, H=8 heads, DH=512
// Round 3: HMMA (mma.sync bf16) GEMMs with bf16x3 split; SIMT attention.
// (tcgen05 is illegal on this harness's PTX target sm_103 — 'a'-only ISA.)
// ---------------------------------------------------------------------------
#define NTOK 4096
#define DMODEL 4096
#define NHEADS 8
#define DHEAD 512
#define ATTN_SCALE 0.04419417382415922f  // 1/sqrt(512)

// fp32 scratch
__device__ float g_Q[(size_t)NTOK * DMODEL];
__device__ float g_K[(size_t)NTOK * DMODEL];
__device__ float g_V[(size_t)NTOK * DMODEL];
__device__ float g_R1[(size_t)NTOK * DMODEL];
// bf16 split activations (row-major [M,K])
__device__ __nv_bfloat16 g_Xhi[(size_t)NTOK * DMODEL];
__device__ __nv_bfloat16 g_Xlo[(size_t)NTOK * DMODEL];
__device__ __nv_bfloat16 g_R1hi[(size_t)NTOK * DMODEL];
__device__ __nv_bfloat16 g_R1lo[(size_t)NTOK * DMODEL];
// bf16 split weights, TRANSPOSED to [N,K] (K-major B)
__device__ __nv_bfloat16 g_Wq_hi[(size_t)DMODEL * DMODEL];
__device__ __nv_bfloat16 g_Wq_lo[(size_t)DMODEL * DMODEL];
__device__ __nv_bfloat16 g_Wk_hi[(size_t)DMODEL * DMODEL];
__device__ __nv_bfloat16 g_Wk_lo[(size_t)DMODEL * DMODEL];
__device__ __nv_bfloat16 g_Wv_hi[(size_t)DMODEL * DMODEL];
__device__ __nv_bfloat16 g_Wv_lo[(size_t)DMODEL * DMODEL];
__device__ __nv_bfloat16 g_Wf_hi[(size_t)DMODEL * DMODEL];
__device__ __nv_bfloat16 g_Wf_lo[(size_t)DMODEL * DMODEL];
__device__ int g_seg_start[NTOK];
__device__ int g_seg_end[NTOK];

// ---------------------------------------------------------------------------
// PTX helpers (all legal on generic sm_103 PTX target: sm_80-era features)
// ---------------------------------------------------------------------------
__device__ __forceinline__ uint32_t smem_u32(const void* p) {
    return (uint32_t)__cvta_generic_to_shared(p);
}
__device__ __forceinline__ uint32_t swz128(uint32_t off) {
    return off ^ ((off >> 3) & 0x70);
}
__device__ __forceinline__ void cp16(uint32_t s, const void* g) {
    asm volatile("cp.async.cg.shared.global [%0], [%1], 16;\n" :: "r"(s), "l"(g));
}
__device__ __forceinline__ void cp_commit() {
    asm volatile("cp.async.commit_group;\n" ::: "memory");
}
__device__ __forceinline__ void cp_wait0() {
    asm volatile("cp.async.wait_group 0;\n" ::: "memory");
}
__device__ __forceinline__ void cp_wait1() {
    asm volatile("cp.async.wait_group 1;\n" ::: "memory");
}
__device__ __forceinline__ void ldsm4(uint32_t* r, uint32_t addr) {
    asm volatile("ldmatrix.sync.aligned.m8n8.x4.shared.b16 {%0,%1,%2,%3}, [%4];"
                 : "=r"(r[0]), "=r"(r[1]), "=r"(r[2]), "=r"(r[3]) : "r"(addr));
}
__device__ __forceinline__ void mma_bf16(float* d, const uint32_t* a,
                                         uint32_t b0, uint32_t b1) {
    asm volatile(
        "mma.sync.aligned.m16n8k16.row.col.f32.bf16.bf16.f32 "
        "{%0,%1,%2,%3}, {%4,%5,%6,%7}, {%8,%9}, {%0,%1,%2,%3};"
        : "+f"(d[0]), "+f"(d[1]), "+f"(d[2]), "+f"(d[3])
        : "r"(a[0]), "r"(a[1]), "r"(a[2]), "r"(a[3]), "r"(b0), "r"(b1));
}

// ---------------------------------------------------------------------------
// Segment table builder (int32 or int64 num_rels)
// ---------------------------------------------------------------------------
__global__ void build_seg_kernel(const int* __restrict__ nr, int count) {
    __shared__ int starts[160];
    __shared__ int nseg;
    if (count > 128) count = 128;
    if (threadIdx.x == 0) {
        long long s32 = 0;
        for (int i = 0; i < count; i++) s32 += nr[i];
        int is64 = (s32 != (long long)NTOK) ? 1 : 0;
        int acc = 0;
        for (int i = 0; i < count; i++) {
            starts[i] = acc;
            int v = is64 ? nr[2 * i] : nr[i];
            acc += v;
        }
        starts[count] = acc;
        nseg = count;
    }
    __syncthreads();
    int ns = nseg;
    for (int t = threadIdx.x; t < NTOK; t += blockDim.x) {
        int lo = 0;
        while (lo + 1 <= ns && starts[lo + 1] <= t) lo++;
        g_seg_start[t] = starts[lo];
        g_seg_end[t] = starts[lo + 1];
    }
}

// ---------------------------------------------------------------------------
// fp32 -> bf16 hi/lo split (row-major)
// ---------------------------------------------------------------------------
__global__ __launch_bounds__(256)
void split_rows(const float* __restrict__ src, __nv_bfloat16* __restrict__ hi,
                __nv_bfloat16* __restrict__ lo, int n4) {
    int i = blockIdx.x * blockDim.x + threadIdx.x;
    if (i >= n4) return;
    float4 v = reinterpret_cast<const float4*>(src)[i];
    float f[4] = {v.x, v.y, v.z, v.w};
    ushort4 h4, l4;
    unsigned short* hp = &h4.x;
    unsigned short* lp = &l4.x;
#pragma unroll
    for (int j = 0; j < 4; j++) {
        __nv_bfloat16 h = __float2bfloat16(f[j]);
        __nv_bfloat16 l = __float2bfloat16(f[j] - __bfloat162float(h));
        hp[j] = __bfloat16_as_ushort(h);
        lp[j] = __bfloat16_as_ushort(l);
    }
    reinterpret_cast<ushort4*>(hi)[i] = h4;
    reinterpret_cast<ushort4*>(lo)[i] = l4;
}

// ---------------------------------------------------------------------------
// W [K,N] fp32 -> transposed [N,K] bf16 hi/lo
// ---------------------------------------------------------------------------
__global__ __launch_bounds__(256)
void transpose_split(const float* __restrict__ W, __nv_bfloat16* __restrict__ Thi,
                     __nv_bfloat16* __restrict__ Tlo) {
    __shared__ float t[32][33];
    int n0 = blockIdx.x * 32;
    int k0 = blockIdx.y * 32;
    int tx = threadIdx.x & 31;
    int ty = threadIdx.x >> 5;
#pragma unroll
    for (int j = 0; j < 32; j += 8)
        t[ty + j][tx] = W[(size_t)(k0 + ty + j) * DMODEL + n0 + tx];
    __syncthreads();
#pragma unroll
    for (int j = 0; j < 32; j += 8) {
        float v = t[tx][ty + j];
        __nv_bfloat16 h = __float2bfloat16(v);
        __nv_bfloat16 l = __float2bfloat16(v - __bfloat162float(h));
        size_t o = (size_t)(n0 + ty + j) * DMODEL + k0 + tx;
        Thi[o] = h;
        Tlo[o] = l;
    }
}

// ---------------------------------------------------------------------------
// HMMA bf16x3 GEMM: C[M,N] = A[M,K] @ (B[N,K])^T + bias (+res)
// CTA tile 128x128, BK=64, 8 warps (2x4), warp tile 64x32 (m16n8k16).
// ---------------------------------------------------------------------------
#define GBM 128
#define GBN 128
#define GBK 64
#define GK DMODEL
#define NCHUNK (GK / GBK)
#define MAT_BYTES 16384       // 128 rows x 128B (64 bf16)
#define STAGE_BYTES 65536     // Ahi/Alo/Bhi/Blo
#define GEMM_SMEM (2 * STAGE_BYTES)
#define EPI_STRIDE 132

__global__ __launch_bounds__(256, 1)
void gemm_bf16x3(const __nv_bfloat16* __restrict__ Ahi, const __nv_bfloat16* __restrict__ Alo,
                 const __nv_bfloat16* __restrict__ Bhi, const __nv_bfloat16* __restrict__ Blo,
                 const float* __restrict__ bias, const float* __restrict__ res,
                 float* __restrict__ C) {
    extern __shared__ char smem[];
    const uint32_t sb = smem_u32(smem);
    const int tid = threadIdx.x;
    const int wid = tid >> 5;
    const int lane = tid & 31;
    const int warpM = wid >> 2;       // 0..1
    const int warpN = wid & 3;        // 0..3
    const int tm = blockIdx.y;
    const int tn = blockIdx.x;

    const char* pAhi = (const char*)(Ahi + (size_t)tm * GBM * GK);
    const char* pAlo = (const char*)(Alo + (size_t)tm * GBM * GK);
    const char* pBhi = (const char*)(Bhi + (size_t)tn * GBN * GK);
    const char* pBlo = (const char*)(Blo + (size_t)tn * GBN * GK);
    const size_t rowstride = (size_t)GK * 2;

    // per-thread load mapping: 128 rows x 8 x 16B per matrix; 4 units/thread/matrix
    auto issue_loads = [&](int chunk, int s) {
        const uint32_t base = sb + s * STAGE_BYTES;
        const size_t koff = (size_t)chunk * GBK * 2;
#pragma unroll
        for (int j = 0; j < 4; j++) {
            int u = tid + 256 * j;
            int row = u >> 3;
            int c = (u & 7) * 16;
            uint32_t so = swz128((uint32_t)(row * 128 + c));
            size_t go = (size_t)row * rowstride + koff + c;
            cp16(base + so, pAhi + go);
            cp16(base + MAT_BYTES + so, pAlo + go);
            cp16(base + 2 * MAT_BYTES + so, pBhi + go);
            cp16(base + 3 * MAT_BYTES + so, pBlo + go);
        }
        cp_commit();
    };

    float acc[4][4][4];
#pragma unroll
    for (int mt = 0; mt < 4; mt++)
#pragma unroll
        for (int nt = 0; nt < 4; nt++)
#pragma unroll
            for (int e = 0; e < 4; e++) acc[mt][nt][e] = 0.0f;

    // per-lane ldmatrix address components
    const int lrow = lane & 15;
    const int lcol = (lane >> 4) * 16;   // byte offset within 32B k-slice

    issue_loads(0, 0);

    for (int i = 0; i < NCHUNK; i++) {
        const int s = i & 1;
        if (i + 1 < NCHUNK) {
            issue_loads(i + 1, 1 - s);
            cp_wait1();
        } else {
            cp_wait0();
        }
        __syncthreads();

        const uint32_t bA_hi = sb + s * STAGE_BYTES;
        const uint32_t bA_lo = bA_hi + MAT_BYTES;
        const uint32_t bB_hi = bA_hi + 2 * MAT_BYTES;
        const uint32_t bB_lo = bA_hi + 3 * MAT_BYTES;

#pragma unroll
        for (int ks = 0; ks < 4; ks++) {
            uint32_t aHi[4][4], aLo[4][4], bHi[2][4], bLo[2][4];
            const int kb = ks * 32 + lcol;
#pragma unroll
            for (int mt = 0; mt < 4; mt++) {
                int row = warpM * 64 + mt * 16 + lrow;
                uint32_t off = swz128((uint32_t)(row * 128 + kb));
                ldsm4(aHi[mt], bA_hi + off);
                ldsm4(aLo[mt], bA_lo + off);
            }
#pragma unroll
            for (int p = 0; p < 2; p++) {
                int row = warpN * 32 + p * 16 + lrow;
                uint32_t off = swz128((uint32_t)(row * 128 + kb));
                ldsm4(bHi[p], bB_hi + off);
                ldsm4(bLo[p], bB_lo + off);
            }
#pragma unroll
            for (int mt = 0; mt < 4; mt++) {
#pragma unroll
                for (int nt = 0; nt < 4; nt++) {
                    const int p = nt >> 1;
                    const int o = nt & 1;
                    mma_bf16(acc[mt][nt], aHi[mt], bHi[p][o], bHi[p][o + 2]);
                    mma_bf16(acc[mt][nt], aHi[mt], bLo[p][o], bLo[p][o + 2]);
                    mma_bf16(acc[mt][nt], aLo[mt], bHi[p][o], bHi[p][o + 2]);
                }
            }
        }
        __syncthreads();
    }

    // ---- epilogue: regs -> smem (transpose to row-major) -> coalesced out ----
    float* sf = reinterpret_cast<float*>(smem);
    const int g = lane >> 2;
    const int t2 = (lane & 3) * 2;
#pragma unroll
    for (int mt = 0; mt < 4; mt++) {
#pragma unroll
        for (int nt = 0; nt < 4; nt++) {
            int row = warpM * 64 + mt * 16 + g;
            int col = warpN * 32 + nt * 8 + t2;
            sf[row * EPI_STRIDE + col] = acc[mt][nt][0];
            sf[row * EPI_STRIDE + col + 1] = acc[mt][nt][1];
            sf[(row + 8) * EPI_STRIDE + col] = acc[mt][nt][2];
            sf[(row + 8) * EPI_STRIDE + col + 1] = acc[mt][nt][3];
        }
    }
    __syncthreads();

    const int orow = tid >> 1;
    const int ocol0 = (tid & 1) * 64;
    const size_t gbase = (size_t)(tm * GBM + orow) * DMODEL + tn * GBN + ocol0;
#pragma unroll
    for (int j = 0; j < 16; j++) {
        int col = ocol0 + j * 4;
        float4 v;
        v.x = sf[orow * EPI_STRIDE + col + 0] + bias[tn * GBN + col + 0];
        v.y = sf[orow * EPI_STRIDE + col + 1] + bias[tn * GBN + col + 1];
        v.z = sf[orow * EPI_STRIDE + col + 2] + bias[tn * GBN + col + 2];
        v.w = sf[orow * EPI_STRIDE + col + 3] + bias[tn * GBN + col + 3];
        if (res != nullptr) {
            float4 r4 = *reinterpret_cast<const float4*>(res + gbase + j * 4);
            v.x += r4.x; v.y += r4.y; v.z += r4.z; v.w += r4.w;
        }
        *reinterpret_cast<float4*>(C + gbase + j * 4) = v;
    }
}

// ---------------------------------------------------------------------------
// Block-diagonal attention, flash-style online softmax (1 warp per (q,h))
// ---------------------------------------------------------------------------
__global__ __launch_bounds__(256)
void attn_kernel(const float* __restrict__ Q, const float* __restrict__ K,
                 const float* __restrict__ V, const float* __restrict__ X,
                 float* __restrict__ R1) {
    const int lane = threadIdx.x & 31;
    const int warp = threadIdx.x >> 5;
    const int q = blockIdx.x * 8 + warp;
    const int h = blockIdx.y;
    if (q >= NTOK) return;

    const int s0 = g_seg_start[q];
    const int s1 = g_seg_end[q];
    const size_t hoff = (size_t)h * DHEAD;
    const float* qrow = Q + (size_t)q * DMODEL + hoff;

    float qreg[16];
#pragma unroll
    for (int i = 0; i < 16; i++) qreg[i] = qrow[lane + 32 * i];

    float m = -1e30f, l = 0.0f;
    float accv[16];
#pragma unroll
    for (int i = 0; i < 16; i++) accv[i] = 0.0f;

    for (int j = s0; j < s1; j++) {
        const float* krow = K + (size_t)j * DMODEL + hoff;
        float s = 0.0f;
#pragma unroll
        for (int i = 0; i < 16; i++) s = fmaf(qreg[i], krow[lane + 32 * i], s);
#pragma unroll
        for (int off = 16; off > 0; off >>= 1)
            s += __shfl_xor_sync(0xFFFFFFFFu, s, off);
        s *= ATTN_SCALE;
        const float mn = fmaxf(m, s);
        const float c = __expf(m - mn);
        const float p = __expf(s - mn);
        l = l * c + p;
        const float* vrow = V + (size_t)j * DMODEL + hoff;
#pragma unroll
        for (int i = 0; i < 16; i++)
            accv[i] = fmaf(accv[i], c, p * vrow[lane + 32 * i]);
        m = mn;
    }

    const float inv = 1.0f / l;
    const float* xr = X + (size_t)q * DMODEL + hoff;
    float* orow = R1 + (size_t)q * DMODEL + hoff;
#pragma unroll
    for (int i = 0; i < 16; i++)
        orow[lane + 32 * i] = accv[i] * inv + xr[lane + 32 * i];
}

// ---------------------------------------------------------------------------
// kernel_launch
// ---------------------------------------------------------------------------
extern "C" void kernel_launch(void* const* d_in, const int* in_sizes, int n_in,
                              void* d_out, int out_size) {
    const float* X   = (const float*)d_in[0];
    const int*   nr  = (const int*)d_in[1];
    const float* Wq  = (const float*)d_in[2];
    const float* bq  = (const float*)d_in[3];
    const float* Wk  = (const float*)d_in[4];
    const float* bk  = (const float*)d_in[5];
    const float* Wv  = (const float*)d_in[6];
    const float* bv  = (const float*)d_in[7];
    const float* Wfc = (const float*)d_in[8];
    const float* bfc = (const float*)d_in[9];
    float* out = (float*)d_out;

    float *Q, *K, *V, *R1;
    __nv_bfloat16 *Xhi, *Xlo, *R1hi, *R1lo;
    __nv_bfloat16 *Wqh, *Wql, *Wkh, *Wkl, *Wvh, *Wvl, *Wfh, *Wfl;
    cudaGetSymbolAddress((void**)&Q,  g_Q);
    cudaGetSymbolAddress((void**)&K,  g_K);
    cudaGetSymbolAddress((void**)&V,  g_V);
    cudaGetSymbolAddress((void**)&R1, g_R1);
    cudaGetSymbolAddress((void**)&Xhi, g_Xhi);
    cudaGetSymbolAddress((void**)&Xlo, g_Xlo);
    cudaGetSymbolAddress((void**)&R1hi, g_R1hi);
    cudaGetSymbolAddress((void**)&R1lo, g_R1lo);
    cudaGetSymbolAddress((void**)&Wqh, g_Wq_hi);
    cudaGetSymbolAddress((void**)&Wql, g_Wq_lo);
    cudaGetSymbolAddress((void**)&Wkh, g_Wk_hi);
    cudaGetSymbolAddress((void**)&Wkl, g_Wk_lo);
    cudaGetSymbolAddress((void**)&Wvh, g_Wv_hi);
    cudaGetSymbolAddress((void**)&Wvl, g_Wv_lo);
    cudaGetSymbolAddress((void**)&Wfh, g_Wf_hi);
    cudaGetSymbolAddress((void**)&Wfl, g_Wf_lo);

    cudaFuncSetAttribute(gemm_bf16x3, cudaFuncAttributeMaxDynamicSharedMemorySize, GEMM_SMEM);

    // 1) segment table
    build_seg_kernel<<<1, 256>>>(nr, in_sizes[1]);

    // 2) bf16 splits / transposed weight splits
    const int n4 = (NTOK * DMODEL) / 4;
    split_rows<<<n4 / 256, 256>>>(X, Xhi, Xlo, n4);
    dim3 tgrid(DMODEL / 32, DMODEL / 32);
    transpose_split<<<tgrid, 256>>>(Wq, Wqh, Wql);
    transpose_split<<<tgrid, 256>>>(Wk, Wkh, Wkl);
    transpose_split<<<tgrid, 256>>>(Wv, Wvh, Wvl);
    transpose_split<<<tgrid, 256>>>(Wfc, Wfh, Wfl);

    // 3) Q/K/V projections (HMMA bf16x3)
    dim3 ggrid(DMODEL / GBN, NTOK / GBM);
    gemm_bf16x3<<<ggrid, 256, GEMM_SMEM>>>(Xhi, Xlo, Wqh, Wql, bq, nullptr, Q);
    gemm_bf16x3<<<ggrid, 256, GEMM_SMEM>>>(Xhi, Xlo, Wkh, Wkl, bk, nullptr, K);
    gemm_bf16x3<<<ggrid, 256, GEMM_SMEM>>>(Xhi, Xlo, Wvh, Wvl, bv, nullptr, V);

    // 4) block-diagonal attention + residual -> R1
    dim3 agrid(NTOK / 8, NHEADS);
    attn_kernel<<<agrid, 256>>>(Q, K, V, X, R1);

    // 5) out = R1 + R1 @ Wfc + bfc
    split_rows<<<n4 / 256, 256>>>(R1, R1hi, R1lo, n4);
    gemm_bf16x3<<<ggrid, 256, GEMM_SMEM>>>(R1hi, R1lo, Wfh, Wfl, bfc, R1, out);
}

// round 4
// speedup vs baseline: 2.7808x; 1.1994x over previous
#include <cuda_runtime.h>
#include <cuda_bf16.h>
#include <math.h>
#include <stdint.h>

// ---------------------------------------------------------------------------
// Self_Attention: N=4096 tokens, D=4096, H=8 heads, DH=512
// Round 4: fused QKV HMMA GEMM (grid-swizzled, 3-stage pipeline),
//          register-blocked attention (4 queries/warp).
// ---------------------------------------------------------------------------
#define NTOK 4096
#define DMODEL 4096
#define NHEADS 8
#define DHEAD 512
#define QKV_N (3 * DMODEL)          // 12288
#define ATTN_SCALE 0.04419417382415922f  // 1/sqrt(512)

// scratch
__device__ float g_QKV[(size_t)NTOK * QKV_N];    // [token][Q(4096) K(4096) V(4096)]
__device__ float g_R1[(size_t)NTOK * DMODEL];
__device__ float g_bqkv[QKV_N];
__device__ __nv_bfloat16 g_Xhi[(size_t)NTOK * DMODEL];
__device__ __nv_bfloat16 g_Xlo[(size_t)NTOK * DMODEL];
__device__ __nv_bfloat16 g_R1hi[(size_t)NTOK * DMODEL];
__device__ __nv_bfloat16 g_R1lo[(size_t)NTOK * DMODEL];
// transposed weights [N,K] bf16; QKV concat along N
__device__ __nv_bfloat16 g_Wqkv_hi[(size_t)QKV_N * DMODEL];
__device__ __nv_bfloat16 g_Wqkv_lo[(size_t)QKV_N * DMODEL];
__device__ __nv_bfloat16 g_Wf_hi[(size_t)DMODEL * DMODEL];
__device__ __nv_bfloat16 g_Wf_lo[(size_t)DMODEL * DMODEL];
__device__ int g_seg_start[NTOK];
__device__ int g_seg_end[NTOK];

// ---------------------------------------------------------------------------
// PTX helpers (sm_80-era features; legal on generic sm_103 PTX target)
// ---------------------------------------------------------------------------
__device__ __forceinline__ uint32_t smem_u32(const void* p) {
    return (uint32_t)__cvta_generic_to_shared(p);
}
__device__ __forceinline__ uint32_t swz128(uint32_t off) {
    return off ^ ((off >> 3) & 0x70);
}
__device__ __forceinline__ void cp16(uint32_t s, const void* g) {
    asm volatile("cp.async.cg.shared.global [%0], [%1], 16;\n" :: "r"(s), "l"(g));
}
__device__ __forceinline__ void cp_commit() {
    asm volatile("cp.async.commit_group;\n" ::: "memory");
}
__device__ __forceinline__ void cp_wait1() {
    asm volatile("cp.async.wait_group 1;\n" ::: "memory");
}
__device__ __forceinline__ void ldsm4(uint32_t* r, uint32_t addr) {
    asm volatile("ldmatrix.sync.aligned.m8n8.x4.shared.b16 {%0,%1,%2,%3}, [%4];"
                 : "=r"(r[0]), "=r"(r[1]), "=r"(r[2]), "=r"(r[3]) : "r"(addr));
}
__device__ __forceinline__ void mma_bf16(float* d, const uint32_t* a,
                                         uint32_t b0, uint32_t b1) {
    asm volatile(
        "mma.sync.aligned.m16n8k16.row.col.f32.bf16.bf16.f32 "
        "{%0,%1,%2,%3}, {%4,%5,%6,%7}, {%8,%9}, {%0,%1,%2,%3};"
        : "+f"(d[0]), "+f"(d[1]), "+f"(d[2]), "+f"(d[3])
        : "r"(a[0]), "r"(a[1]), "r"(a[2]), "r"(a[3]), "r"(b0), "r"(b1));
}

// ---------------------------------------------------------------------------
// Segment table builder (int32 or int64 num_rels)
// ---------------------------------------------------------------------------
__global__ void build_seg_kernel(const int* __restrict__ nr, int count) {
    __shared__ int starts[160];
    __shared__ int nseg;
    if (count > 128) count = 128;
    if (threadIdx.x == 0) {
        long long s32 = 0;
        for (int i = 0; i < count; i++) s32 += nr[i];
        int is64 = (s32 != (long long)NTOK) ? 1 : 0;
        int acc = 0;
        for (int i = 0; i < count; i++) {
            starts[i] = acc;
            int v = is64 ? nr[2 * i] : nr[i];
            acc += v;
        }
        starts[count] = acc;
        nseg = count;
    }
    __syncthreads();
    int ns = nseg;
    for (int t = threadIdx.x; t < NTOK; t += blockDim.x) {
        int lo = 0;
        while (lo + 1 <= ns && starts[lo + 1] <= t) lo++;
        g_seg_start[t] = starts[lo];
        g_seg_end[t] = starts[lo + 1];
    }
}

// ---------------------------------------------------------------------------
// fp32 -> bf16 hi/lo split (row-major)
// ---------------------------------------------------------------------------
__global__ __launch_bounds__(256)
void split_rows(const float* __restrict__ src, __nv_bfloat16* __restrict__ hi,
                __nv_bfloat16* __restrict__ lo, int n4) {
    int i = blockIdx.x * blockDim.x + threadIdx.x;
    if (i >= n4) return;
    float4 v = reinterpret_cast<const float4*>(src)[i];
    float f[4] = {v.x, v.y, v.z, v.w};
    ushort4 h4, l4;
    unsigned short* hp = &h4.x;
    unsigned short* lp = &l4.x;
#pragma unroll
    for (int j = 0; j < 4; j++) {
        __nv_bfloat16 h = __float2bfloat16(f[j]);
        __nv_bfloat16 l = __float2bfloat16(f[j] - __bfloat162float(h));
        hp[j] = __bfloat16_as_ushort(h);
        lp[j] = __bfloat16_as_ushort(l);
    }
    reinterpret_cast<ushort4*>(hi)[i] = h4;
    reinterpret_cast<ushort4*>(lo)[i] = l4;
}

// ---------------------------------------------------------------------------
// W [K,N] fp32 -> transposed [N,K] bf16 hi/lo (dst may be offset into concat)
// ---------------------------------------------------------------------------
__global__ __launch_bounds__(256)
void transpose_split(const float* __restrict__ W, __nv_bfloat16* __restrict__ Thi,
                     __nv_bfloat16* __restrict__ Tlo) {
    __shared__ float t[32][33];
    int n0 = blockIdx.x * 32;
    int k0 = blockIdx.y * 32;
    int tx = threadIdx.x & 31;
    int ty = threadIdx.x >> 5;
#pragma unroll
    for (int j = 0; j < 32; j += 8)
        t[ty + j][tx] = W[(size_t)(k0 + ty + j) * DMODEL + n0 + tx];
    __syncthreads();
#pragma unroll
    for (int j = 0; j < 32; j += 8) {
        float v = t[tx][ty + j];
        __nv_bfloat16 h = __float2bfloat16(v);
        __nv_bfloat16 l = __float2bfloat16(v - __bfloat162float(h));
        size_t o = (size_t)(n0 + ty + j) * DMODEL + k0 + tx;
        Thi[o] = h;
        Tlo[o] = l;
    }
}

__global__ void concat_bias(const float* __restrict__ bq, const float* __restrict__ bk,
                            const float* __restrict__ bv, float* __restrict__ dst) {
    int i = blockIdx.x * 256 + threadIdx.x;
    if (i >= QKV_N) return;
    dst[i] = (i < DMODEL) ? bq[i] : (i < 2 * DMODEL ? bk[i - DMODEL] : bv[i - 2 * DMODEL]);
}

// ---------------------------------------------------------------------------
// HMMA bf16x3 GEMM: C[M,Ntot] = A[M,4096] @ (B[Ntot,4096])^T + bias (+res)
// CTA tile 128x128, BK=64, 8 warps (2x4), 3-stage cp.async pipeline,
// grid-swizzled (GROUP_M=16) 1D launch.
// ---------------------------------------------------------------------------
#define GBM 128
#define GBN 128
#define GBK 64
#define GK DMODEL
#define NCHUNK (GK / GBK)
#define MAT_BYTES 16384       // 128 rows x 128B
#define STAGE_BYTES 65536     // Ahi/Alo/Bhi/Blo
#define NSTAGE 3
#define GEMM_SMEM (NSTAGE * STAGE_BYTES)
#define EPI_STRIDE 132
#define GROUP_M 16

__global__ __launch_bounds__(256, 1)
void gemm_bf16x3(const __nv_bfloat16* __restrict__ Ahi, const __nv_bfloat16* __restrict__ Alo,
                 const __nv_bfloat16* __restrict__ Bhi, const __nv_bfloat16* __restrict__ Blo,
                 const float* __restrict__ bias, const float* __restrict__ res,
                 float* __restrict__ C, int Ntot) {
    extern __shared__ char smem[];
    const uint32_t sb = smem_u32(smem);
    const int tid = threadIdx.x;
    const int wid = tid >> 5;
    const int lane = tid & 31;
    const int warpM = wid >> 2;
    const int warpN = wid & 3;

    // grid swizzle: GROUP_M M-tiles per N-sweep
    const int ntn = Ntot / GBN;
    const int per_group = GROUP_M * ntn;
    const int bid = blockIdx.x;
    const int tm = (bid / per_group) * GROUP_M + (bid % per_group) % GROUP_M;
    const int tn = (bid % per_group) / GROUP_M;

    const char* pAhi = (const char*)(Ahi + (size_t)tm * GBM * GK);
    const char* pAlo = (const char*)(Alo + (size_t)tm * GBM * GK);
    const char* pBhi = (const char*)(Bhi + (size_t)tn * GBN * GK);
    const char* pBlo = (const char*)(Blo + (size_t)tn * GBN * GK);
    const size_t rowstride = (size_t)GK * 2;

    auto issue_loads = [&](int chunk, int s) {
        const uint32_t base = sb + s * STAGE_BYTES;
        const size_t koff = (size_t)chunk * GBK * 2;
#pragma unroll
        for (int j = 0; j < 4; j++) {
            int u = tid + 256 * j;
            int row = u >> 3;
            int c = (u & 7) * 16;
            uint32_t so = swz128((uint32_t)(row * 128 + c));
            size_t go = (size_t)row * rowstride + koff + c;
            cp16(base + so, pAhi + go);
            cp16(base + MAT_BYTES + so, pAlo + go);
            cp16(base + 2 * MAT_BYTES + so, pBhi + go);
            cp16(base + 3 * MAT_BYTES + so, pBlo + go);
        }
        cp_commit();
    };

    float acc[4][4][4];
#pragma unroll
    for (int mt = 0; mt < 4; mt++)
#pragma unroll
        for (int nt = 0; nt < 4; nt++)
#pragma unroll
            for (int e = 0; e < 4; e++) acc[mt][nt][e] = 0.0f;

    const int lrow = lane & 15;
    const int lcol = (lane >> 4) * 16;

    issue_loads(0, 0);
    issue_loads(1, 1);

    for (int i = 0; i < NCHUNK; i++) {
        cp_wait1();                 // chunk i resident
        __syncthreads();
        const int s = i % NSTAGE;

        const uint32_t bA_hi = sb + s * STAGE_BYTES;
        const uint32_t bA_lo = bA_hi + MAT_BYTES;
        const uint32_t bB_hi = bA_hi + 2 * MAT_BYTES;
        const uint32_t bB_lo = bA_hi + 3 * MAT_BYTES;

#pragma unroll
        for (int ks = 0; ks < 4; ks++) {
            uint32_t aHi[4][4], aLo[4][4], bHi[2][4], bLo[2][4];
            const int kb = ks * 32 + lcol;
#pragma unroll
            for (int mt = 0; mt < 4; mt++) {
                int row = warpM * 64 + mt * 16 + lrow;
                uint32_t off = swz128((uint32_t)(row * 128 + kb));
                ldsm4(aHi[mt], bA_hi + off);
                ldsm4(aLo[mt], bA_lo + off);
            }
#pragma unroll
            for (int p = 0; p < 2; p++) {
                int row = warpN * 32 + p * 16 + lrow;
                uint32_t off = swz128((uint32_t)(row * 128 + kb));
                ldsm4(bHi[p], bB_hi + off);
                ldsm4(bLo[p], bB_lo + off);
            }
#pragma unroll
            for (int mt = 0; mt < 4; mt++) {
#pragma unroll
                for (int nt = 0; nt < 4; nt++) {
                    const int p = nt >> 1;
                    const int o = nt & 1;
                    mma_bf16(acc[mt][nt], aHi[mt], bHi[p][o], bHi[p][o + 2]);
                    mma_bf16(acc[mt][nt], aHi[mt], bLo[p][o], bLo[p][o + 2]);
                    mma_bf16(acc[mt][nt], aLo[mt], bHi[p][o], bHi[p][o + 2]);
                }
            }
        }
        // prefetch chunk i+2 into stage (i+2)%3 (stage of i-1, all done computing)
        if (i + 2 < NCHUNK) issue_loads(i + 2, (i + 2) % NSTAGE);
    }
    __syncthreads();

    // ---- epilogue: regs -> smem -> coalesced out ----
    float* sf = reinterpret_cast<float*>(smem);
    const int g = lane >> 2;
    const int t2 = (lane & 3) * 2;
#pragma unroll
    for (int mt = 0; mt < 4; mt++) {
#pragma unroll
        for (int nt = 0; nt < 4; nt++) {
            int row = warpM * 64 + mt * 16 + g;
            int col = warpN * 32 + nt * 8 + t2;
            sf[row * EPI_STRIDE + col] = acc[mt][nt][0];
            sf[row * EPI_STRIDE + col + 1] = acc[mt][nt][1];
            sf[(row + 8) * EPI_STRIDE + col] = acc[mt][nt][2];
            sf[(row + 8) * EPI_STRIDE + col + 1] = acc[mt][nt][3];
        }
    }
    __syncthreads();

    const int orow = tid >> 1;
    const int ocol0 = (tid & 1) * 64;
    const size_t gbase = (size_t)(tm * GBM + orow) * Ntot + (size_t)tn * GBN + ocol0;
    const size_t rbase = (size_t)(tm * GBM + orow) * DMODEL + (size_t)tn * GBN + ocol0;
#pragma unroll
    for (int j = 0; j < 16; j++) {
        int col = ocol0 + j * 4;
        float4 v;
        v.x = sf[orow * EPI_STRIDE + col + 0] + bias[tn * GBN + col + 0];
        v.y = sf[orow * EPI_STRIDE + col + 1] + bias[tn * GBN + col + 1];
        v.z = sf[orow * EPI_STRIDE + col + 2] + bias[tn * GBN + col + 2];
        v.w = sf[orow * EPI_STRIDE + col + 3] + bias[tn * GBN + col + 3];
        if (res != nullptr) {
            float4 r4 = *reinterpret_cast<const float4*>(res + rbase + j * 4);
            v.x += r4.x; v.y += r4.y; v.z += r4.z; v.w += r4.w;
        }
        *reinterpret_cast<float4*>(C + gbase + j * 4) = v;
    }
}

// ---------------------------------------------------------------------------
// Block-diagonal attention, register-blocked: 1 warp handles 4 queries.
// QKV strided layout: row q -> [Q(4096) | K(4096) | V(4096)].
// ---------------------------------------------------------------------------
__global__ __launch_bounds__(256)
void attn_kernel(const float* __restrict__ QKV, const float* __restrict__ X,
                 float* __restrict__ R1) {
    const int lane = threadIdx.x & 31;
    const int warp = threadIdx.x >> 5;
    const int q0 = blockIdx.x * 32 + warp * 4;
    const int h = blockIdx.y;
    const size_t hoff = (size_t)h * DHEAD;

    int s0[4], s1[4];
    float qreg[4][16];
#pragma unroll
    for (int i = 0; i < 4; i++) {
        const int q = q0 + i;
        s0[i] = g_seg_start[q];
        s1[i] = g_seg_end[q];
        const float* qrow = QKV + (size_t)q * QKV_N + hoff;
#pragma unroll
        for (int d = 0; d < 16; d++) qreg[i][d] = qrow[lane + 32 * d];
    }
    int jmin = min(min(s0[0], s0[1]), min(s0[2], s0[3]));
    int jmax = max(max(s1[0], s1[1]), max(s1[2], s1[3]));

    float m[4] = {-1e30f, -1e30f, -1e30f, -1e30f};
    float l[4] = {0.f, 0.f, 0.f, 0.f};
    float accv[4][16];
#pragma unroll
    for (int i = 0; i < 4; i++)
#pragma unroll
        for (int d = 0; d < 16; d++) accv[i][d] = 0.0f;

    for (int j = jmin; j < jmax; j++) {
        const float* krow = QKV + (size_t)j * QKV_N + DMODEL + hoff;
        float kr[16];
#pragma unroll
        for (int d = 0; d < 16; d++) kr[d] = krow[lane + 32 * d];

        float s[4] = {0.f, 0.f, 0.f, 0.f};
#pragma unroll
        for (int d = 0; d < 16; d++) {
#pragma unroll
            for (int i = 0; i < 4; i++) s[i] = fmaf(qreg[i][d], kr[d], s[i]);
        }
#pragma unroll
        for (int off = 16; off > 0; off >>= 1) {
#pragma unroll
            for (int i = 0; i < 4; i++) s[i] += __shfl_xor_sync(0xFFFFFFFFu, s[i], off);
        }

        const float* vrow = QKV + (size_t)j * QKV_N + 2 * DMODEL + hoff;
        float vr[16];
#pragma unroll
        for (int d = 0; d < 16; d++) vr[d] = vrow[lane + 32 * d];

#pragma unroll
        for (int i = 0; i < 4; i++) {
            if (j >= s0[i] && j < s1[i]) {
                const float sc = s[i] * ATTN_SCALE;
                const float mn = fmaxf(m[i], sc);
                const float c = __expf(m[i] - mn);
                const float p = __expf(sc - mn);
                l[i] = l[i] * c + p;
#pragma unroll
                for (int d = 0; d < 16; d++)
                    accv[i][d] = fmaf(accv[i][d], c, p * vr[d]);
                m[i] = mn;
            }
        }
    }

#pragma unroll
    for (int i = 0; i < 4; i++) {
        const int q = q0 + i;
        const float inv = 1.0f / l[i];
        const float* xr = X + (size_t)q * DMODEL + hoff;
        float* orow = R1 + (size_t)q * DMODEL + hoff;
#pragma unroll
        for (int d = 0; d < 16; d++)
            orow[lane + 32 * d] = accv[i][d] * inv + xr[lane + 32 * d];
    }
}

// ---------------------------------------------------------------------------
// kernel_launch
// ---------------------------------------------------------------------------
extern "C" void kernel_launch(void* const* d_in, const int* in_sizes, int n_in,
                              void* d_out, int out_size) {
    const float* X   = (const float*)d_in[0];
    const int*   nr  = (const int*)d_in[1];
    const float* Wq  = (const float*)d_in[2];
    const float* bq  = (const float*)d_in[3];
    const float* Wk  = (const float*)d_in[4];
    const float* bk  = (const float*)d_in[5];
    const float* Wv  = (const float*)d_in[6];
    const float* bv  = (const float*)d_in[7];
    const float* Wfc = (const float*)d_in[8];
    const float* bfc = (const float*)d_in[9];
    float* out = (float*)d_out;

    float *QKV, *R1, *bqkv;
    __nv_bfloat16 *Xhi, *Xlo, *R1hi, *R1lo, *Wqkvh, *Wqkvl, *Wfh, *Wfl;
    cudaGetSymbolAddress((void**)&QKV, g_QKV);
    cudaGetSymbolAddress((void**)&R1, g_R1);
    cudaGetSymbolAddress((void**)&bqkv, g_bqkv);
    cudaGetSymbolAddress((void**)&Xhi, g_Xhi);
    cudaGetSymbolAddress((void**)&Xlo, g_Xlo);
    cudaGetSymbolAddress((void**)&R1hi, g_R1hi);
    cudaGetSymbolAddress((void**)&R1lo, g_R1lo);
    cudaGetSymbolAddress((void**)&Wqkvh, g_Wqkv_hi);
    cudaGetSymbolAddress((void**)&Wqkvl, g_Wqkv_lo);
    cudaGetSymbolAddress((void**)&Wfh, g_Wf_hi);
    cudaGetSymbolAddress((void**)&Wfl, g_Wf_lo);

    cudaFuncSetAttribute(gemm_bf16x3, cudaFuncAttributeMaxDynamicSharedMemorySize, GEMM_SMEM);

    // 1) segment table + bias concat
    build_seg_kernel<<<1, 256>>>(nr, in_sizes[1]);
    concat_bias<<<(QKV_N + 255) / 256, 256>>>(bq, bk, bv, bqkv);

    // 2) bf16 splits / transposed weight splits (into QKV concat)
    const int n4 = (NTOK * DMODEL) / 4;
    split_rows<<<n4 / 256, 256>>>(X, Xhi, Xlo, n4);
    dim3 tgrid(DMODEL / 32, DMODEL / 32);
    transpose_split<<<tgrid, 256>>>(Wq, Wqkvh, Wqkvl);
    transpose_split<<<tgrid, 256>>>(Wk, Wqkvh + (size_t)DMODEL * DMODEL,
                                         Wqkvl + (size_t)DMODEL * DMODEL);
    transpose_split<<<tgrid, 256>>>(Wv, Wqkvh + (size_t)2 * DMODEL * DMODEL,
                                         Wqkvl + (size_t)2 * DMODEL * DMODEL);
    transpose_split<<<tgrid, 256>>>(Wfc, Wfh, Wfl);

    // 3) fused QKV projection (one GEMM, Ntot=12288)
    const int qkv_tiles = (QKV_N / GBN) * (NTOK / GBM);
    gemm_bf16x3<<<qkv_tiles, 256, GEMM_SMEM>>>(Xhi, Xlo, Wqkvh, Wqkvl, bqkv,
                                               nullptr, QKV, QKV_N);

    // 4) block-diagonal attention + residual -> R1
    dim3 agrid(NTOK / 32, NHEADS);
    attn_kernel<<<agrid, 256>>>(QKV, X, R1);

    // 5) out = R1 + R1 @ Wfc + bfc
    split_rows<<<n4 / 256, 256>>>(R1, R1hi, R1lo, n4);
    const int fc_tiles = (DMODEL / GBN) * (NTOK / GBM);
    gemm_bf16x3<<<fc_tiles, 256, GEMM_SMEM>>>(R1hi, R1lo, Wfh, Wfl, bfc, R1, out,
                                              DMODEL);
}

// round 5
// speedup vs baseline: 3.6557x; 1.3146x over previous
#include <cuda_runtime.h>
#include <cuda_fp16.h>
#include <math.h>
#include <stdint.h>

// ---------------------------------------------------------------------------
// Self_Attention: N=4096 tokens, D=4096, H=8 heads, DH=512
// Round 5: fp16x2 HMMA GEMMs (A=fp16 hi only, B=fp16 hi+lo): 2 MMA passes
//          instead of 3; launch order arranged so ncu (-s 5) profiles the
//          QKV GEMM. Register-blocked SIMT attention.
// ---------------------------------------------------------------------------
#define NTOK 4096
#define DMODEL 4096
#define NHEADS 8
#define DHEAD 512
#define QKV_N (3 * DMODEL)          // 12288
#define ATTN_SCALE 0.04419417382415922f  // 1/sqrt(512)

// scratch
__device__ float g_QKV[(size_t)NTOK * QKV_N];
__device__ float g_R1[(size_t)NTOK * DMODEL];
__device__ float g_bqkv[QKV_N];
__device__ __half g_Xh[(size_t)NTOK * DMODEL];
__device__ __half g_R1h[(size_t)NTOK * DMODEL];
// transposed weights [N,K] fp16 hi/lo; QKV concat along N
__device__ __half g_Wqkv_hi[(size_t)QKV_N * DMODEL];
__device__ __half g_Wqkv_lo[(size_t)QKV_N * DMODEL];
__device__ __half g_Wf_hi[(size_t)DMODEL * DMODEL];
__device__ __half g_Wf_lo[(size_t)DMODEL * DMODEL];
__device__ int g_seg_start[NTOK];
__device__ int g_seg_end[NTOK];

// ---------------------------------------------------------------------------
// PTX helpers (sm_80-era features; legal on generic sm_103 PTX target)
// ---------------------------------------------------------------------------
__device__ __forceinline__ uint32_t smem_u32(const void* p) {
    return (uint32_t)__cvta_generic_to_shared(p);
}
__device__ __forceinline__ uint32_t swz128(uint32_t off) {
    return off ^ ((off >> 3) & 0x70);
}
__device__ __forceinline__ void cp16(uint32_t s, const void* g) {
    asm volatile("cp.async.cg.shared.global [%0], [%1], 16;\n" :: "r"(s), "l"(g));
}
__device__ __forceinline__ void cp_commit() {
    asm volatile("cp.async.commit_group;\n" ::: "memory");
}
__device__ __forceinline__ void cp_wait1() {
    asm volatile("cp.async.wait_group 1;\n" ::: "memory");
}
__device__ __forceinline__ void ldsm4(uint32_t* r, uint32_t addr) {
    asm volatile("ldmatrix.sync.aligned.m8n8.x4.shared.b16 {%0,%1,%2,%3}, [%4];"
                 : "=r"(r[0]), "=r"(r[1]), "=r"(r[2]), "=r"(r[3]) : "r"(addr));
}
__device__ __forceinline__ void mma_f16(float* d, const uint32_t* a,
                                        uint32_t b0, uint32_t b1) {
    asm volatile(
        "mma.sync.aligned.m16n8k16.row.col.f32.f16.f16.f32 "
        "{%0,%1,%2,%3}, {%4,%5,%6,%7}, {%8,%9}, {%0,%1,%2,%3};"
        : "+f"(d[0]), "+f"(d[1]), "+f"(d[2]), "+f"(d[3])
        : "r"(a[0]), "r"(a[1]), "r"(a[2]), "r"(a[3]), "r"(b0), "r"(b1));
}

// ---------------------------------------------------------------------------
// Segment table builder (int32 or int64 num_rels)
// ---------------------------------------------------------------------------
__global__ void build_seg_kernel(const int* __restrict__ nr, int count) {
    __shared__ int starts[160];
    __shared__ int nseg;
    if (count > 128) count = 128;
    if (threadIdx.x == 0) {
        long long s32 = 0;
        for (int i = 0; i < count; i++) s32 += nr[i];
        int is64 = (s32 != (long long)NTOK) ? 1 : 0;
        int acc = 0;
        for (int i = 0; i < count; i++) {
            starts[i] = acc;
            int v = is64 ? nr[2 * i] : nr[i];
            acc += v;
        }
        starts[count] = acc;
        nseg = count;
    }
    __syncthreads();
    int ns = nseg;
    for (int t = threadIdx.x; t < NTOK; t += blockDim.x) {
        int lo = 0;
        while (lo + 1 <= ns && starts[lo + 1] <= t) lo++;
        g_seg_start[t] = starts[lo];
        g_seg_end[t] = starts[lo + 1];
    }
}

// ---------------------------------------------------------------------------
// fp32 -> fp16 convert (activations: hi only)
// ---------------------------------------------------------------------------
__global__ __launch_bounds__(256)
void convert_h(const float* __restrict__ src, __half* __restrict__ dst, int n4) {
    int i = blockIdx.x * blockDim.x + threadIdx.x;
    if (i >= n4) return;
    float4 v = reinterpret_cast<const float4*>(src)[i];
    __half2 a = __floats2half2_rn(v.x, v.y);
    __half2 b = __floats2half2_rn(v.z, v.w);
    uint2 o;
    o.x = *reinterpret_cast<uint32_t*>(&a);
    o.y = *reinterpret_cast<uint32_t*>(&b);
    reinterpret_cast<uint2*>(dst)[i] = o;
}

// ---------------------------------------------------------------------------
// W [K,N] fp32 -> transposed [N,K] fp16 hi/lo
// ---------------------------------------------------------------------------
__global__ __launch_bounds__(256)
void transpose_split(const float* __restrict__ W, __half* __restrict__ Thi,
                     __half* __restrict__ Tlo) {
    __shared__ float t[32][33];
    int n0 = blockIdx.x * 32;
    int k0 = blockIdx.y * 32;
    int tx = threadIdx.x & 31;
    int ty = threadIdx.x >> 5;
#pragma unroll
    for (int j = 0; j < 32; j += 8)
        t[ty + j][tx] = W[(size_t)(k0 + ty + j) * DMODEL + n0 + tx];
    __syncthreads();
#pragma unroll
    for (int j = 0; j < 32; j += 8) {
        float v = t[tx][ty + j];
        __half h = __float2half_rn(v);
        __half l = __float2half_rn(v - __half2float(h));
        size_t o = (size_t)(n0 + ty + j) * DMODEL + k0 + tx;
        Thi[o] = h;
        Tlo[o] = l;
    }
}

__global__ void concat_bias(const float* __restrict__ bq, const float* __restrict__ bk,
                            const float* __restrict__ bv, float* __restrict__ dst) {
    int i = blockIdx.x * 256 + threadIdx.x;
    if (i >= QKV_N) return;
    dst[i] = (i < DMODEL) ? bq[i] : (i < 2 * DMODEL ? bk[i - DMODEL] : bv[i - 2 * DMODEL]);
}

// ---------------------------------------------------------------------------
// HMMA fp16x2 GEMM: C[M,Ntot] = A[M,4096] @ (B[Ntot,4096])^T + bias (+res)
// A fp16 (hi only); B fp16 hi+lo. CTA tile 128x128, BK=64, 8 warps (2x4),
// 3-stage cp.async pipeline, grid-swizzled (GROUP_M=16) 1D launch.
// ---------------------------------------------------------------------------
#define GBM 128
#define GBN 128
#define GBK 64
#define GK DMODEL
#define NCHUNK (GK / GBK)
#define MAT_BYTES 16384       // 128 rows x 128B
#define STAGE_BYTES 49152     // Ah + Bhi + Blo
#define NSTAGE 3
#define GEMM_SMEM (NSTAGE * STAGE_BYTES)
#define EPI_STRIDE 132
#define GROUP_M 16

__global__ __launch_bounds__(256, 1)
void gemm_f16x2(const __half* __restrict__ Ah,
                const __half* __restrict__ Bhi, const __half* __restrict__ Blo,
                const float* __restrict__ bias, const float* __restrict__ res,
                float* __restrict__ C, int Ntot) {
    extern __shared__ char smem[];
    const uint32_t sb = smem_u32(smem);
    const int tid = threadIdx.x;
    const int wid = tid >> 5;
    const int lane = tid & 31;
    const int warpM = wid >> 2;
    const int warpN = wid & 3;

    const int ntn = Ntot / GBN;
    const int per_group = GROUP_M * ntn;
    const int bid = blockIdx.x;
    const int tm = (bid / per_group) * GROUP_M + (bid % per_group) % GROUP_M;
    const int tn = (bid % per_group) / GROUP_M;

    const char* pAh  = (const char*)(Ah  + (size_t)tm * GBM * GK);
    const char* pBhi = (const char*)(Bhi + (size_t)tn * GBN * GK);
    const char* pBlo = (const char*)(Blo + (size_t)tn * GBN * GK);
    const size_t rowstride = (size_t)GK * 2;

    auto issue_loads = [&](int chunk, int s) {
        const uint32_t base = sb + s * STAGE_BYTES;
        const size_t koff = (size_t)chunk * GBK * 2;
#pragma unroll
        for (int j = 0; j < 4; j++) {
            int u = tid + 256 * j;
            int row = u >> 3;
            int c = (u & 7) * 16;
            uint32_t so = swz128((uint32_t)(row * 128 + c));
            size_t go = (size_t)row * rowstride + koff + c;
            cp16(base + so, pAh + go);
            cp16(base + MAT_BYTES + so, pBhi + go);
            cp16(base + 2 * MAT_BYTES + so, pBlo + go);
        }
        cp_commit();
    };

    float acc[4][4][4];
#pragma unroll
    for (int mt = 0; mt < 4; mt++)
#pragma unroll
        for (int nt = 0; nt < 4; nt++)
#pragma unroll
            for (int e = 0; e < 4; e++) acc[mt][nt][e] = 0.0f;

    const int lrow = lane & 15;
    const int lcol = (lane >> 4) * 16;

    issue_loads(0, 0);
    issue_loads(1, 1);

    for (int i = 0; i < NCHUNK; i++) {
        cp_wait1();
        __syncthreads();
        const int s = i % NSTAGE;

        const uint32_t bA  = sb + s * STAGE_BYTES;
        const uint32_t bBh = bA + MAT_BYTES;
        const uint32_t bBl = bA + 2 * MAT_BYTES;

#pragma unroll
        for (int ks = 0; ks < 4; ks++) {
            uint32_t aH[4][4], bHi[2][4], bLo[2][4];
            const int kb = ks * 32 + lcol;
#pragma unroll
            for (int mt = 0; mt < 4; mt++) {
                int row = warpM * 64 + mt * 16 + lrow;
                uint32_t off = swz128((uint32_t)(row * 128 + kb));
                ldsm4(aH[mt], bA + off);
            }
#pragma unroll
            for (int p = 0; p < 2; p++) {
                int row = warpN * 32 + p * 16 + lrow;
                uint32_t off = swz128((uint32_t)(row * 128 + kb));
                ldsm4(bHi[p], bBh + off);
                ldsm4(bLo[p], bBl + off);
            }
#pragma unroll
            for (int mt = 0; mt < 4; mt++) {
#pragma unroll
                for (int nt = 0; nt < 4; nt++) {
                    const int p = nt >> 1;
                    const int o = nt & 1;
                    mma_f16(acc[mt][nt], aH[mt], bHi[p][o], bHi[p][o + 2]);
                    mma_f16(acc[mt][nt], aH[mt], bLo[p][o], bLo[p][o + 2]);
                }
            }
        }
        if (i + 2 < NCHUNK) issue_loads(i + 2, (i + 2) % NSTAGE);
    }
    __syncthreads();

    // ---- epilogue: regs -> smem -> coalesced out ----
    float* sf = reinterpret_cast<float*>(smem);
    const int g = lane >> 2;
    const int t2 = (lane & 3) * 2;
#pragma unroll
    for (int mt = 0; mt < 4; mt++) {
#pragma unroll
        for (int nt = 0; nt < 4; nt++) {
            int row = warpM * 64 + mt * 16 + g;
            int col = warpN * 32 + nt * 8 + t2;
            sf[row * EPI_STRIDE + col] = acc[mt][nt][0];
            sf[row * EPI_STRIDE + col + 1] = acc[mt][nt][1];
            sf[(row + 8) * EPI_STRIDE + col] = acc[mt][nt][2];
            sf[(row + 8) * EPI_STRIDE + col + 1] = acc[mt][nt][3];
        }
    }
    __syncthreads();

    const int orow = tid >> 1;
    const int ocol0 = (tid & 1) * 64;
    const size_t gbase = (size_t)(tm * GBM + orow) * Ntot + (size_t)tn * GBN + ocol0;
    const size_t rbase = (size_t)(tm * GBM + orow) * DMODEL + (size_t)tn * GBN + ocol0;
#pragma unroll
    for (int j = 0; j < 16; j++) {
        int col = ocol0 + j * 4;
        float4 v;
        v.x = sf[orow * EPI_STRIDE + col + 0] + bias[tn * GBN + col + 0];
        v.y = sf[orow * EPI_STRIDE + col + 1] + bias[tn * GBN + col + 1];
        v.z = sf[orow * EPI_STRIDE + col + 2] + bias[tn * GBN + col + 2];
        v.w = sf[orow * EPI_STRIDE + col + 3] + bias[tn * GBN + col + 3];
        if (res != nullptr) {
            float4 r4 = *reinterpret_cast<const float4*>(res + rbase + j * 4);
            v.x += r4.x; v.y += r4.y; v.z += r4.z; v.w += r4.w;
        }
        *reinterpret_cast<float4*>(C + gbase + j * 4) = v;
    }
}

// ---------------------------------------------------------------------------
// Block-diagonal attention, register-blocked: 1 warp handles 4 queries.
// ---------------------------------------------------------------------------
__global__ __launch_bounds__(256)
void attn_kernel(const float* __restrict__ QKV, const float* __restrict__ X,
                 float* __restrict__ R1) {
    const int lane = threadIdx.x & 31;
    const int warp = threadIdx.x >> 5;
    const int q0 = blockIdx.x * 32 + warp * 4;
    const int h = blockIdx.y;
    const size_t hoff = (size_t)h * DHEAD;

    int s0[4], s1[4];
    float qreg[4][16];
#pragma unroll
    for (int i = 0; i < 4; i++) {
        const int q = q0 + i;
        s0[i] = g_seg_start[q];
        s1[i] = g_seg_end[q];
        const float* qrow = QKV + (size_t)q * QKV_N + hoff;
#pragma unroll
        for (int d = 0; d < 16; d++) qreg[i][d] = qrow[lane + 32 * d];
    }
    int jmin = min(min(s0[0], s0[1]), min(s0[2], s0[3]));
    int jmax = max(max(s1[0], s1[1]), max(s1[2], s1[3]));

    float m[4] = {-1e30f, -1e30f, -1e30f, -1e30f};
    float l[4] = {0.f, 0.f, 0.f, 0.f};
    float accv[4][16];
#pragma unroll
    for (int i = 0; i < 4; i++)
#pragma unroll
        for (int d = 0; d < 16; d++) accv[i][d] = 0.0f;

    for (int j = jmin; j < jmax; j++) {
        const float* krow = QKV + (size_t)j * QKV_N + DMODEL + hoff;
        float kr[16];
#pragma unroll
        for (int d = 0; d < 16; d++) kr[d] = krow[lane + 32 * d];

        float s[4] = {0.f, 0.f, 0.f, 0.f};
#pragma unroll
        for (int d = 0; d < 16; d++) {
#pragma unroll
            for (int i = 0; i < 4; i++) s[i] = fmaf(qreg[i][d], kr[d], s[i]);
        }
#pragma unroll
        for (int off = 16; off > 0; off >>= 1) {
#pragma unroll
            for (int i = 0; i < 4; i++) s[i] += __shfl_xor_sync(0xFFFFFFFFu, s[i], off);
        }

        const float* vrow = QKV + (size_t)j * QKV_N + 2 * DMODEL + hoff;
        float vr[16];
#pragma unroll
        for (int d = 0; d < 16; d++) vr[d] = vrow[lane + 32 * d];

#pragma unroll
        for (int i = 0; i < 4; i++) {
            if (j >= s0[i] && j < s1[i]) {
                const float sc = s[i] * ATTN_SCALE;
                const float mn = fmaxf(m[i], sc);
                const float c = __expf(m[i] - mn);
                const float p = __expf(sc - mn);
                l[i] = l[i] * c + p;
#pragma unroll
                for (int d = 0; d < 16; d++)
                    accv[i][d] = fmaf(accv[i][d], c, p * vr[d]);
                m[i] = mn;
            }
        }
    }

#pragma unroll
    for (int i = 0; i < 4; i++) {
        const int q = q0 + i;
        const float inv = 1.0f / l[i];
        const float* xr = X + (size_t)q * DMODEL + hoff;
        float* orow = R1 + (size_t)q * DMODEL + hoff;
#pragma unroll
        for (int d = 0; d < 16; d++)
            orow[lane + 32 * d] = accv[i][d] * inv + xr[lane + 32 * d];
    }
}

// ---------------------------------------------------------------------------
// kernel_launch — order chosen so launch #6 (ncu -s 5 -c 1) is the QKV GEMM.
// ---------------------------------------------------------------------------
extern "C" void kernel_launch(void* const* d_in, const int* in_sizes, int n_in,
                              void* d_out, int out_size) {
    const float* X   = (const float*)d_in[0];
    const int*   nr  = (const int*)d_in[1];
    const float* Wq  = (const float*)d_in[2];
    const float* bq  = (const float*)d_in[3];
    const float* Wk  = (const float*)d_in[4];
    const float* bk  = (const float*)d_in[5];
    const float* Wv  = (const float*)d_in[6];
    const float* bv  = (const float*)d_in[7];
    const float* Wfc = (const float*)d_in[8];
    const float* bfc = (const float*)d_in[9];
    float* out = (float*)d_out;

    float *QKV, *R1, *bqkv;
    __half *Xh, *R1h, *Wqkvh, *Wqkvl, *Wfh, *Wfl;
    cudaGetSymbolAddress((void**)&QKV, g_QKV);
    cudaGetSymbolAddress((void**)&R1, g_R1);
    cudaGetSymbolAddress((void**)&bqkv, g_bqkv);
    cudaGetSymbolAddress((void**)&Xh, g_Xh);
    cudaGetSymbolAddress((void**)&R1h, g_R1h);
    cudaGetSymbolAddress((void**)&Wqkvh, g_Wqkv_hi);
    cudaGetSymbolAddress((void**)&Wqkvl, g_Wqkv_lo);
    cudaGetSymbolAddress((void**)&Wfh, g_Wf_hi);
    cudaGetSymbolAddress((void**)&Wfl, g_Wf_lo);

    cudaFuncSetAttribute(gemm_f16x2, cudaFuncAttributeMaxDynamicSharedMemorySize, GEMM_SMEM);

    const int n4 = (NTOK * DMODEL) / 4;
    dim3 tgrid(DMODEL / 32, DMODEL / 32);

    // 1..5
    concat_bias<<<(QKV_N + 255) / 256, 256>>>(bq, bk, bv, bqkv);
    convert_h<<<n4 / 256, 256>>>(X, Xh, n4);
    transpose_split<<<tgrid, 256>>>(Wq, Wqkvh, Wqkvl);
    transpose_split<<<tgrid, 256>>>(Wk, Wqkvh + (size_t)DMODEL * DMODEL,
                                         Wqkvl + (size_t)DMODEL * DMODEL);
    transpose_split<<<tgrid, 256>>>(Wv, Wqkvh + (size_t)2 * DMODEL * DMODEL,
                                         Wqkvl + (size_t)2 * DMODEL * DMODEL);

    // 6: fused QKV projection (profiled by ncu)
    const int qkv_tiles = (QKV_N / GBN) * (NTOK / GBM);
    gemm_f16x2<<<qkv_tiles, 256, GEMM_SMEM>>>(Xh, Wqkvh, Wqkvl, bqkv,
                                              nullptr, QKV, QKV_N);

    // 7..8: segments + attention
    build_seg_kernel<<<1, 256>>>(nr, in_sizes[1]);
    dim3 agrid(NTOK / 32, NHEADS);
    attn_kernel<<<agrid, 256>>>(QKV, X, R1);

    // 9..11: FC weights + convert + FC GEMM
    transpose_split<<<tgrid, 256>>>(Wfc, Wfh, Wfl);
    convert_h<<<n4 / 256, 256>>>(R1, R1h, n4);
    const int fc_tiles = (DMODEL / GBN) * (NTOK / GBM);
    gemm_f16x2<<<fc_tiles, 256, GEMM_SMEM>>>(R1h, Wfh, Wfl, bfc, R1, out, DMODEL);
}

// round 6
// speedup vs baseline: 3.7838x; 1.0350x over previous
#include <cuda_runtime.h>
#include <cuda_fp16.h>
#include <math.h>
#include <stdint.h>

// ---------------------------------------------------------------------------
// Self_Attention: N=4096 tokens, D=4096, H=8 heads, DH=512
// Round 6: 256x128 CTA / 64x64 warp HMMA fp16x2 GEMM; fused prep;
//          attention epilogue emits fp16 copy of R1.
// ---------------------------------------------------------------------------
#define NTOK 4096
#define DMODEL 4096
#define NHEADS 8
#define DHEAD 512
#define QKV_N (3 * DMODEL)
#define ATTN_SCALE 0.04419417382415922f  // 1/sqrt(512)

__device__ float g_QKV[(size_t)NTOK * QKV_N];
__device__ float g_R1[(size_t)NTOK * DMODEL];
__device__ float g_bqkv[QKV_N];
__device__ __half g_Xh[(size_t)NTOK * DMODEL];
__device__ __half g_R1h[(size_t)NTOK * DMODEL];
__device__ __half g_Wqkv_hi[(size_t)QKV_N * DMODEL];
__device__ __half g_Wqkv_lo[(size_t)QKV_N * DMODEL];
__device__ __half g_Wf_hi[(size_t)DMODEL * DMODEL];
__device__ __half g_Wf_lo[(size_t)DMODEL * DMODEL];
__device__ int g_seg_start[NTOK];
__device__ int g_seg_end[NTOK];

// ---------------------------------------------------------------------------
// PTX helpers (sm_80-era features; legal on generic sm_103 PTX target)
// ---------------------------------------------------------------------------
__device__ __forceinline__ uint32_t smem_u32(const void* p) {
    return (uint32_t)__cvta_generic_to_shared(p);
}
__device__ __forceinline__ uint32_t swz128(uint32_t off) {
    return off ^ ((off >> 3) & 0x70);
}
__device__ __forceinline__ void cp16(uint32_t s, const void* g) {
    asm volatile("cp.async.cg.shared.global [%0], [%1], 16;\n" :: "r"(s), "l"(g));
}
__device__ __forceinline__ void cp_commit() {
    asm volatile("cp.async.commit_group;\n" ::: "memory");
}
__device__ __forceinline__ void cp_wait1() {
    asm volatile("cp.async.wait_group 1;\n" ::: "memory");
}
__device__ __forceinline__ void ldsm4(uint32_t* r, uint32_t addr) {
    asm volatile("ldmatrix.sync.aligned.m8n8.x4.shared.b16 {%0,%1,%2,%3}, [%4];"
                 : "=r"(r[0]), "=r"(r[1]), "=r"(r[2]), "=r"(r[3]) : "r"(addr));
}
__device__ __forceinline__ void mma_f16(float* d, const uint32_t* a,
                                        uint32_t b0, uint32_t b1) {
    asm volatile(
        "mma.sync.aligned.m16n8k16.row.col.f32.f16.f16.f32 "
        "{%0,%1,%2,%3}, {%4,%5,%6,%7}, {%8,%9}, {%0,%1,%2,%3};"
        : "+f"(d[0]), "+f"(d[1]), "+f"(d[2]), "+f"(d[3])
        : "r"(a[0]), "r"(a[1]), "r"(a[2]), "r"(a[3]), "r"(b0), "r"(b1));
}

// ---------------------------------------------------------------------------
// Segment table builder (int32 or int64 num_rels)
// ---------------------------------------------------------------------------
__global__ void build_seg_kernel(const int* __restrict__ nr, int count) {
    __shared__ int starts[160];
    __shared__ int nseg;
    if (count > 128) count = 128;
    if (threadIdx.x == 0) {
        long long s32 = 0;
        for (int i = 0; i < count; i++) s32 += nr[i];
        int is64 = (s32 != (long long)NTOK) ? 1 : 0;
        int acc = 0;
        for (int i = 0; i < count; i++) {
            starts[i] = acc;
            int v = is64 ? nr[2 * i] : nr[i];
            acc += v;
        }
        starts[count] = acc;
        nseg = count;
    }
    __syncthreads();
    int ns = nseg;
    for (int t = threadIdx.x; t < NTOK; t += blockDim.x) {
        int lo = 0;
        while (lo + 1 <= ns && starts[lo + 1] <= t) lo++;
        g_seg_start[t] = starts[lo];
        g_seg_end[t] = starts[lo + 1];
    }
}

// ---------------------------------------------------------------------------
// fp32 -> fp16 convert
// ---------------------------------------------------------------------------
__global__ __launch_bounds__(256)
void convert_h(const float* __restrict__ src, __half* __restrict__ dst, int n4) {
    int i = blockIdx.x * blockDim.x + threadIdx.x;
    if (i >= n4) return;
    float4 v = reinterpret_cast<const float4*>(src)[i];
    __half2 a = __floats2half2_rn(v.x, v.y);
    __half2 b = __floats2half2_rn(v.z, v.w);
    uint2 o;
    o.x = *reinterpret_cast<uint32_t*>(&a);
    o.y = *reinterpret_cast<uint32_t*>(&b);
    reinterpret_cast<uint2*>(dst)[i] = o;
}

// ---------------------------------------------------------------------------
// Fused QKV weight transpose+split: grid.z selects Wq/Wk/Wv
// W [K,N] fp32 -> [N,K] fp16 hi/lo at dst offset z*D*D
// ---------------------------------------------------------------------------
__global__ __launch_bounds__(256)
void transpose_split3(const float* __restrict__ W0, const float* __restrict__ W1,
                      const float* __restrict__ W2, __half* __restrict__ Thi,
                      __half* __restrict__ Tlo) {
    const float* W = (blockIdx.z == 0) ? W0 : (blockIdx.z == 1 ? W1 : W2);
    __half* hi = Thi + (size_t)blockIdx.z * DMODEL * DMODEL;
    __half* lo = Tlo + (size_t)blockIdx.z * DMODEL * DMODEL;
    __shared__ float t[32][33];
    int n0 = blockIdx.x * 32;
    int k0 = blockIdx.y * 32;
    int tx = threadIdx.x & 31;
    int ty = threadIdx.x >> 5;
#pragma unroll
    for (int j = 0; j < 32; j += 8)
        t[ty + j][tx] = W[(size_t)(k0 + ty + j) * DMODEL + n0 + tx];
    __syncthreads();
#pragma unroll
    for (int j = 0; j < 32; j += 8) {
        float v = t[tx][ty + j];
        __half h = __float2half_rn(v);
        __half l = __float2half_rn(v - __half2float(h));
        size_t o = (size_t)(n0 + ty + j) * DMODEL + k0 + tx;
        hi[o] = h;
        lo[o] = l;
    }
}

__global__ __launch_bounds__(256)
void transpose_split(const float* __restrict__ W, __half* __restrict__ Thi,
                     __half* __restrict__ Tlo) {
    __shared__ float t[32][33];
    int n0 = blockIdx.x * 32;
    int k0 = blockIdx.y * 32;
    int tx = threadIdx.x & 31;
    int ty = threadIdx.x >> 5;
#pragma unroll
    for (int j = 0; j < 32; j += 8)
        t[ty + j][tx] = W[(size_t)(k0 + ty + j) * DMODEL + n0 + tx];
    __syncthreads();
#pragma unroll
    for (int j = 0; j < 32; j += 8) {
        float v = t[tx][ty + j];
        __half h = __float2half_rn(v);
        __half l = __float2half_rn(v - __half2float(h));
        size_t o = (size_t)(n0 + ty + j) * DMODEL + k0 + tx;
        Thi[o] = h;
        Tlo[o] = l;
    }
}

__global__ void concat_bias(const float* __restrict__ bq, const float* __restrict__ bk,
                            const float* __restrict__ bv, float* __restrict__ dst) {
    int i = blockIdx.x * 256 + threadIdx.x;
    if (i >= QKV_N) return;
    dst[i] = (i < DMODEL) ? bq[i] : (i < 2 * DMODEL ? bk[i - DMODEL] : bv[i - 2 * DMODEL]);
}

// ---------------------------------------------------------------------------
// HMMA fp16x2 GEMM: C[M,Ntot] = A[M,4096] @ (B[Ntot,4096])^T + bias (+res)
// CTA tile 256x128, 8 warps (4x2), warp tile 64x64, BK=64, 3-stage cp.async.
// ---------------------------------------------------------------------------
#define GBM 256
#define GBN 128
#define GBK 64
#define GK DMODEL
#define NCHUNK (GK / GBK)
#define A_BYTES 32768         // 256 rows x 128B
#define B_BYTES 16384         // 128 rows x 128B
#define STAGE_BYTES (A_BYTES + 2 * B_BYTES)   // 65536
#define NSTAGE 3
#define GEMM_SMEM (NSTAGE * STAGE_BYTES)      // 196608
#define EPI_STRIDE 132
#define NTM (NTOK / GBM)      // 16

__global__ __launch_bounds__(256, 1)
void gemm_f16x2(const __half* __restrict__ Ah,
                const __half* __restrict__ Bhi, const __half* __restrict__ Blo,
                const float* __restrict__ bias, const float* __restrict__ res,
                float* __restrict__ C, int Ntot) {
    extern __shared__ char smem[];
    const uint32_t sb = smem_u32(smem);
    const int tid = threadIdx.x;
    const int wid = tid >> 5;
    const int lane = tid & 31;
    const int warpM = wid >> 1;       // 0..3
    const int warpN = wid & 1;        // 0..1

    // tm-fastest ordering: one wave covers all A (L2-resident)
    const int tm = blockIdx.x % NTM;
    const int tn = blockIdx.x / NTM;

    const char* pAh  = (const char*)(Ah  + (size_t)tm * GBM * GK);
    const char* pBhi = (const char*)(Bhi + (size_t)tn * GBN * GK);
    const char* pBlo = (const char*)(Blo + (size_t)tn * GBN * GK);
    const size_t rowstride = (size_t)GK * 2;

    auto issue_loads = [&](int chunk, int s) {
        const uint32_t base = sb + s * STAGE_BYTES;
        const size_t koff = (size_t)chunk * GBK * 2;
        // A: 256 rows x 8 units = 2048 units, 8 per thread
#pragma unroll
        for (int j = 0; j < 8; j++) {
            int u = tid + 256 * j;
            int row = u >> 3;
            int c = (u & 7) * 16;
            uint32_t so = swz128((uint32_t)(row * 128 + c));
            cp16(base + so, pAh + (size_t)row * rowstride + koff + c);
        }
        // B hi/lo: 128 rows x 8 units = 1024 units each, 4 per thread
#pragma unroll
        for (int j = 0; j < 4; j++) {
            int u = tid + 256 * j;
            int row = u >> 3;
            int c = (u & 7) * 16;
            uint32_t so = swz128((uint32_t)(row * 128 + c));
            size_t go = (size_t)row * rowstride + koff + c;
            cp16(base + A_BYTES + so, pBhi + go);
            cp16(base + A_BYTES + B_BYTES + so, pBlo + go);
        }
        cp_commit();
    };

    float acc[4][8][4];
#pragma unroll
    for (int mt = 0; mt < 4; mt++)
#pragma unroll
        for (int nt = 0; nt < 8; nt++)
#pragma unroll
            for (int e = 0; e < 4; e++) acc[mt][nt][e] = 0.0f;

    const int lrow = lane & 15;
    const int lcol = (lane >> 4) * 16;

    issue_loads(0, 0);
    issue_loads(1, 1);

    for (int i = 0; i < NCHUNK; i++) {
        cp_wait1();
        __syncthreads();
        const int s = i % NSTAGE;
        const uint32_t bA  = sb + s * STAGE_BYTES;
        const uint32_t bBh = bA + A_BYTES;
        const uint32_t bBl = bA + A_BYTES + B_BYTES;

#pragma unroll
        for (int ks = 0; ks < 4; ks++) {
            const int kb = ks * 32 + lcol;
            uint32_t aH[4][4], bH[4][4], bL[4][4];
#pragma unroll
            for (int mt = 0; mt < 4; mt++) {
                int row = warpM * 64 + mt * 16 + lrow;
                ldsm4(aH[mt], bA + swz128((uint32_t)(row * 128 + kb)));
            }
#pragma unroll
            for (int p = 0; p < 4; p++) {
                int row = warpN * 64 + p * 16 + lrow;
                uint32_t off = swz128((uint32_t)(row * 128 + kb));
                ldsm4(bH[p], bBh + off);
                ldsm4(bL[p], bBl + off);
            }
#pragma unroll
            for (int mt = 0; mt < 4; mt++) {
#pragma unroll
                for (int nt = 0; nt < 8; nt++) {
                    const int p = nt >> 1;
                    const int o = nt & 1;
                    mma_f16(acc[mt][nt], aH[mt], bH[p][o], bH[p][o + 2]);
                    mma_f16(acc[mt][nt], aH[mt], bL[p][o], bL[p][o + 2]);
                }
            }
        }
        if (i + 2 < NCHUNK) issue_loads(i + 2, (i + 2) % NSTAGE);
    }
    __syncthreads();

    // ---- epilogue: regs -> smem -> coalesced out ----
    float* sf = reinterpret_cast<float*>(smem);
    const int g = lane >> 2;
    const int t2 = (lane & 3) * 2;
#pragma unroll
    for (int mt = 0; mt < 4; mt++) {
#pragma unroll
        for (int nt = 0; nt < 8; nt++) {
            int row = warpM * 64 + mt * 16 + g;
            int col = warpN * 64 + nt * 8 + t2;
            sf[row * EPI_STRIDE + col] = acc[mt][nt][0];
            sf[row * EPI_STRIDE + col + 1] = acc[mt][nt][1];
            sf[(row + 8) * EPI_STRIDE + col] = acc[mt][nt][2];
            sf[(row + 8) * EPI_STRIDE + col + 1] = acc[mt][nt][3];
        }
    }
    __syncthreads();

    // 256 threads -> one row each, 128 cols
    const int orow = tid;
    const size_t gbase = (size_t)(tm * GBM + orow) * Ntot + (size_t)tn * GBN;
    const size_t rbase = (size_t)(tm * GBM + orow) * DMODEL + (size_t)tn * GBN;
#pragma unroll
    for (int j = 0; j < 32; j++) {
        int col = j * 4;
        float4 v;
        v.x = sf[orow * EPI_STRIDE + col + 0] + bias[tn * GBN + col + 0];
        v.y = sf[orow * EPI_STRIDE + col + 1] + bias[tn * GBN + col + 1];
        v.z = sf[orow * EPI_STRIDE + col + 2] + bias[tn * GBN + col + 2];
        v.w = sf[orow * EPI_STRIDE + col + 3] + bias[tn * GBN + col + 3];
        if (res != nullptr) {
            float4 r4 = *reinterpret_cast<const float4*>(res + rbase + col);
            v.x += r4.x; v.y += r4.y; v.z += r4.z; v.w += r4.w;
        }
        *reinterpret_cast<float4*>(C + gbase + col) = v;
    }
}

// ---------------------------------------------------------------------------
// Block-diagonal attention, 4 queries/warp; epilogue writes R1 (fp32) + R1h (fp16)
// ---------------------------------------------------------------------------
__global__ __launch_bounds__(256)
void attn_kernel(const float* __restrict__ QKV, const float* __restrict__ X,
                 float* __restrict__ R1, __half* __restrict__ R1h) {
    const int lane = threadIdx.x & 31;
    const int warp = threadIdx.x >> 5;
    const int q0 = blockIdx.x * 32 + warp * 4;
    const int h = blockIdx.y;
    const size_t hoff = (size_t)h * DHEAD;

    int s0[4], s1[4];
    float qreg[4][16];
#pragma unroll
    for (int i = 0; i < 4; i++) {
        const int q = q0 + i;
        s0[i] = g_seg_start[q];
        s1[i] = g_seg_end[q];
        const float* qrow = QKV + (size_t)q * QKV_N + hoff;
#pragma unroll
        for (int d = 0; d < 16; d++) qreg[i][d] = qrow[lane + 32 * d];
    }
    int jmin = min(min(s0[0], s0[1]), min(s0[2], s0[3]));
    int jmax = max(max(s1[0], s1[1]), max(s1[2], s1[3]));

    float m[4] = {-1e30f, -1e30f, -1e30f, -1e30f};
    float l[4] = {0.f, 0.f, 0.f, 0.f};
    float accv[4][16];
#pragma unroll
    for (int i = 0; i < 4; i++)
#pragma unroll
        for (int d = 0; d < 16; d++) accv[i][d] = 0.0f;

    for (int j = jmin; j < jmax; j++) {
        const float* krow = QKV + (size_t)j * QKV_N + DMODEL + hoff;
        float kr[16];
#pragma unroll
        for (int d = 0; d < 16; d++) kr[d] = krow[lane + 32 * d];

        float s[4] = {0.f, 0.f, 0.f, 0.f};
#pragma unroll
        for (int d = 0; d < 16; d++) {
#pragma unroll
            for (int i = 0; i < 4; i++) s[i] = fmaf(qreg[i][d], kr[d], s[i]);
        }
#pragma unroll
        for (int off = 16; off > 0; off >>= 1) {
#pragma unroll
            for (int i = 0; i < 4; i++) s[i] += __shfl_xor_sync(0xFFFFFFFFu, s[i], off);
        }

        const float* vrow = QKV + (size_t)j * QKV_N + 2 * DMODEL + hoff;
        float vr[16];
#pragma unroll
        for (int d = 0; d < 16; d++) vr[d] = vrow[lane + 32 * d];

#pragma unroll
        for (int i = 0; i < 4; i++) {
            if (j >= s0[i] && j < s1[i]) {
                const float sc = s[i] * ATTN_SCALE;
                const float mn = fmaxf(m[i], sc);
                const float c = __expf(m[i] - mn);
                const float p = __expf(sc - mn);
                l[i] = l[i] * c + p;
#pragma unroll
                for (int d = 0; d < 16; d++)
                    accv[i][d] = fmaf(accv[i][d], c, p * vr[d]);
                m[i] = mn;
            }
        }
    }

#pragma unroll
    for (int i = 0; i < 4; i++) {
        const int q = q0 + i;
        const float inv = 1.0f / l[i];
        const float* xr = X + (size_t)q * DMODEL + hoff;
        float* orow = R1 + (size_t)q * DMODEL + hoff;
        __half* hrow = R1h + (size_t)q * DMODEL + hoff;
#pragma unroll
        for (int d = 0; d < 16; d++) {
            float o = accv[i][d] * inv + xr[lane + 32 * d];
            orow[lane + 32 * d] = o;
            hrow[lane + 32 * d] = __float2half_rn(o);
        }
    }
}

// ---------------------------------------------------------------------------
// kernel_launch
// ---------------------------------------------------------------------------
extern "C" void kernel_launch(void* const* d_in, const int* in_sizes, int n_in,
                              void* d_out, int out_size) {
    const float* X   = (const float*)d_in[0];
    const int*   nr  = (const int*)d_in[1];
    const float* Wq  = (const float*)d_in[2];
    const float* bq  = (const float*)d_in[3];
    const float* Wk  = (const float*)d_in[4];
    const float* bk  = (const float*)d_in[5];
    const float* Wv  = (const float*)d_in[6];
    const float* bv  = (const float*)d_in[7];
    const float* Wfc = (const float*)d_in[8];
    const float* bfc = (const float*)d_in[9];
    float* out = (float*)d_out;

    float *QKV, *R1, *bqkv;
    __half *Xh, *R1h, *Wqkvh, *Wqkvl, *Wfh, *Wfl;
    cudaGetSymbolAddress((void**)&QKV, g_QKV);
    cudaGetSymbolAddress((void**)&R1, g_R1);
    cudaGetSymbolAddress((void**)&bqkv, g_bqkv);
    cudaGetSymbolAddress((void**)&Xh, g_Xh);
    cudaGetSymbolAddress((void**)&R1h, g_R1h);
    cudaGetSymbolAddress((void**)&Wqkvh, g_Wqkv_hi);
    cudaGetSymbolAddress((void**)&Wqkvl, g_Wqkv_lo);
    cudaGetSymbolAddress((void**)&Wfh, g_Wf_hi);
    cudaGetSymbolAddress((void**)&Wfl, g_Wf_lo);

    cudaFuncSetAttribute(gemm_f16x2, cudaFuncAttributeMaxDynamicSharedMemorySize, GEMM_SMEM);

    const int n4 = (NTOK * DMODEL) / 4;

    // prep
    concat_bias<<<(QKV_N + 255) / 256, 256>>>(bq, bk, bv, bqkv);
    convert_h<<<n4 / 256, 256>>>(X, Xh, n4);
    dim3 tgrid3(DMODEL / 32, DMODEL / 32, 3);
    transpose_split3<<<tgrid3, 256>>>(Wq, Wk, Wv, Wqkvh, Wqkvl);
    build_seg_kernel<<<1, 256>>>(nr, in_sizes[1]);

    // fused QKV projection
    const int qkv_tiles = NTM * (QKV_N / GBN);
    gemm_f16x2<<<qkv_tiles, 256, GEMM_SMEM>>>(Xh, Wqkvh, Wqkvl, bqkv,
                                              nullptr, QKV, QKV_N);

    // attention (+ fp16 R1 copy in epilogue)
    dim3 agrid(NTOK / 32, NHEADS);
    attn_kernel<<<agrid, 256>>>(QKV, X, R1, R1h);

    // FC
    dim3 tgrid(DMODEL / 32, DMODEL / 32);
    transpose_split<<<tgrid, 256>>>(Wfc, Wfh, Wfl);
    const int fc_tiles = NTM * (DMODEL / GBN);
    gemm_f16x2<<<fc_tiles, 256, GEMM_SMEM>>>(R1h, Wfh, Wfl, bfc, R1, out, DMODEL);
}

// round 7
// speedup vs baseline: 5.2811x; 1.3957x over previous
#include <cuda_runtime.h>
#include <cuda_fp16.h>
#include <math.h>
#include <stdint.h>

// ---------------------------------------------------------------------------
// Self_Attention: N=4096 tokens, D=4096, H=8 heads, DH=512
// Round 7: single-pass fp16 HMMA GEMM (A fp16, B fp16), 4-stage pipeline.
// Error budget: A-rounding (2^-12) + B-rounding (2^-12) -> ~3e-4 rel_err.
// ---------------------------------------------------------------------------
#define NTOK 4096
#define DMODEL 4096
#define NHEADS 8
#define DHEAD 512
#define QKV_N (3 * DMODEL)
#define ATTN_SCALE 0.04419417382415922f  // 1/sqrt(512)

__device__ float g_QKV[(size_t)NTOK * QKV_N];
__device__ float g_R1[(size_t)NTOK * DMODEL];
__device__ float g_bqkv[QKV_N];
__device__ __half g_Xh[(size_t)NTOK * DMODEL];
__device__ __half g_R1h[(size_t)NTOK * DMODEL];
__device__ __half g_Wqkv[(size_t)QKV_N * DMODEL];   // [N,K] fp16
__device__ __half g_Wf[(size_t)DMODEL * DMODEL];    // [N,K] fp16
__device__ int g_seg_start[NTOK];
__device__ int g_seg_end[NTOK];

// ---------------------------------------------------------------------------
// PTX helpers
// ---------------------------------------------------------------------------
__device__ __forceinline__ uint32_t smem_u32(const void* p) {
    return (uint32_t)__cvta_generic_to_shared(p);
}
__device__ __forceinline__ uint32_t swz128(uint32_t off) {
    return off ^ ((off >> 3) & 0x70);
}
__device__ __forceinline__ void cp16(uint32_t s, const void* g) {
    asm volatile("cp.async.cg.shared.global [%0], [%1], 16;\n" :: "r"(s), "l"(g));
}
__device__ __forceinline__ void cp_commit() {
    asm volatile("cp.async.commit_group;\n" ::: "memory");
}
__device__ __forceinline__ void cp_wait2() {
    asm volatile("cp.async.wait_group 2;\n" ::: "memory");
}
__device__ __forceinline__ void ldsm4(uint32_t* r, uint32_t addr) {
    asm volatile("ldmatrix.sync.aligned.m8n8.x4.shared.b16 {%0,%1,%2,%3}, [%4];"
                 : "=r"(r[0]), "=r"(r[1]), "=r"(r[2]), "=r"(r[3]) : "r"(addr));
}
__device__ __forceinline__ void mma_f16(float* d, const uint32_t* a,
                                        uint32_t b0, uint32_t b1) {
    asm volatile(
        "mma.sync.aligned.m16n8k16.row.col.f32.f16.f16.f32 "
        "{%0,%1,%2,%3}, {%4,%5,%6,%7}, {%8,%9}, {%0,%1,%2,%3};"
        : "+f"(d[0]), "+f"(d[1]), "+f"(d[2]), "+f"(d[3])
        : "r"(a[0]), "r"(a[1]), "r"(a[2]), "r"(a[3]), "r"(b0), "r"(b1));
}

// ---------------------------------------------------------------------------
// Segment table builder (int32 or int64 num_rels)
// ---------------------------------------------------------------------------
__global__ void build_seg_kernel(const int* __restrict__ nr, int count) {
    __shared__ int starts[160];
    __shared__ int nseg;
    if (count > 128) count = 128;
    if (threadIdx.x == 0) {
        long long s32 = 0;
        for (int i = 0; i < count; i++) s32 += nr[i];
        int is64 = (s32 != (long long)NTOK) ? 1 : 0;
        int acc = 0;
        for (int i = 0; i < count; i++) {
            starts[i] = acc;
            int v = is64 ? nr[2 * i] : nr[i];
            acc += v;
        }
        starts[count] = acc;
        nseg = count;
    }
    __syncthreads();
    int ns = nseg;
    for (int t = threadIdx.x; t < NTOK; t += blockDim.x) {
        int lo = 0;
        while (lo + 1 <= ns && starts[lo + 1] <= t) lo++;
        g_seg_start[t] = starts[lo];
        g_seg_end[t] = starts[lo + 1];
    }
}

// ---------------------------------------------------------------------------
// fp32 -> fp16 convert
// ---------------------------------------------------------------------------
__global__ __launch_bounds__(256)
void convert_h(const float* __restrict__ src, __half* __restrict__ dst, int n4) {
    int i = blockIdx.x * blockDim.x + threadIdx.x;
    if (i >= n4) return;
    float4 v = reinterpret_cast<const float4*>(src)[i];
    __half2 a = __floats2half2_rn(v.x, v.y);
    __half2 b = __floats2half2_rn(v.z, v.w);
    uint2 o;
    o.x = *reinterpret_cast<uint32_t*>(&a);
    o.y = *reinterpret_cast<uint32_t*>(&b);
    reinterpret_cast<uint2*>(dst)[i] = o;
}

// ---------------------------------------------------------------------------
// Fused weight transpose+convert: grid.z selects Wq/Wk/Wv (or single W)
// W [K,N] fp32 -> [N,K] fp16
// ---------------------------------------------------------------------------
__global__ __launch_bounds__(256)
void transpose_conv3(const float* __restrict__ W0, const float* __restrict__ W1,
                     const float* __restrict__ W2, __half* __restrict__ T) {
    const float* W = (blockIdx.z == 0) ? W0 : (blockIdx.z == 1 ? W1 : W2);
    __half* dst = T + (size_t)blockIdx.z * DMODEL * DMODEL;
    __shared__ float t[32][33];
    int n0 = blockIdx.x * 32;
    int k0 = blockIdx.y * 32;
    int tx = threadIdx.x & 31;
    int ty = threadIdx.x >> 5;
#pragma unroll
    for (int j = 0; j < 32; j += 8)
        t[ty + j][tx] = W[(size_t)(k0 + ty + j) * DMODEL + n0 + tx];
    __syncthreads();
#pragma unroll
    for (int j = 0; j < 32; j += 8) {
        float v = t[tx][ty + j];
        dst[(size_t)(n0 + ty + j) * DMODEL + k0 + tx] = __float2half_rn(v);
    }
}

__global__ void concat_bias(const float* __restrict__ bq, const float* __restrict__ bk,
                            const float* __restrict__ bv, float* __restrict__ dst) {
    int i = blockIdx.x * 256 + threadIdx.x;
    if (i >= QKV_N) return;
    dst[i] = (i < DMODEL) ? bq[i] : (i < 2 * DMODEL ? bk[i - DMODEL] : bv[i - 2 * DMODEL]);
}

// ---------------------------------------------------------------------------
// Single-pass fp16 HMMA GEMM: C[M,Ntot] = A[M,4096] @ (B[Ntot,4096])^T + bias (+res)
// CTA tile 256x128, 8 warps (4x2), warp tile 64x64, BK=64, 4-stage cp.async.
// ---------------------------------------------------------------------------
#define GBM 256
#define GBN 128
#define GBK 64
#define GK DMODEL
#define NCHUNK (GK / GBK)
#define A_BYTES 32768         // 256 rows x 128B
#define B_BYTES 16384         // 128 rows x 128B
#define STAGE_BYTES (A_BYTES + B_BYTES)       // 49152
#define NSTAGE 4
#define GEMM_SMEM (NSTAGE * STAGE_BYTES)      // 196608
#define EPI_STRIDE 132
#define NTM (NTOK / GBM)      // 16

__global__ __launch_bounds__(256, 1)
void gemm_f16(const __half* __restrict__ Ah, const __half* __restrict__ Bh,
              const float* __restrict__ bias, const float* __restrict__ res,
              float* __restrict__ C, int Ntot) {
    extern __shared__ char smem[];
    const uint32_t sb = smem_u32(smem);
    const int tid = threadIdx.x;
    const int wid = tid >> 5;
    const int lane = tid & 31;
    const int warpM = wid >> 1;       // 0..3
    const int warpN = wid & 1;        // 0..1

    const int tm = blockIdx.x % NTM;
    const int tn = blockIdx.x / NTM;

    const char* pAh = (const char*)(Ah + (size_t)tm * GBM * GK);
    const char* pBh = (const char*)(Bh + (size_t)tn * GBN * GK);
    const size_t rowstride = (size_t)GK * 2;

    auto issue_loads = [&](int chunk, int s) {
        const uint32_t base = sb + s * STAGE_BYTES;
        const size_t koff = (size_t)chunk * GBK * 2;
#pragma unroll
        for (int j = 0; j < 8; j++) {
            int u = tid + 256 * j;
            int row = u >> 3;
            int c = (u & 7) * 16;
            uint32_t so = swz128((uint32_t)(row * 128 + c));
            cp16(base + so, pAh + (size_t)row * rowstride + koff + c);
        }
#pragma unroll
        for (int j = 0; j < 4; j++) {
            int u = tid + 256 * j;
            int row = u >> 3;
            int c = (u & 7) * 16;
            uint32_t so = swz128((uint32_t)(row * 128 + c));
            cp16(base + A_BYTES + so, pBh + (size_t)row * rowstride + koff + c);
        }
        cp_commit();
    };

    float acc[4][8][4];
#pragma unroll
    for (int mt = 0; mt < 4; mt++)
#pragma unroll
        for (int nt = 0; nt < 8; nt++)
#pragma unroll
            for (int e = 0; e < 4; e++) acc[mt][nt][e] = 0.0f;

    const int lrow = lane & 15;
    const int lcol = (lane >> 4) * 16;

    issue_loads(0, 0);
    issue_loads(1, 1);
    issue_loads(2, 2);

    for (int i = 0; i < NCHUNK; i++) {
        cp_wait2();              // chunk i resident (<=2 groups pending)
        __syncthreads();
        const int s = i % NSTAGE;
        const uint32_t bA = sb + s * STAGE_BYTES;
        const uint32_t bB = bA + A_BYTES;

#pragma unroll
        for (int ks = 0; ks < 4; ks++) {
            const int kb = ks * 32 + lcol;
            uint32_t aH[4][4], bH[4][4];
#pragma unroll
            for (int mt = 0; mt < 4; mt++) {
                int row = warpM * 64 + mt * 16 + lrow;
                ldsm4(aH[mt], bA + swz128((uint32_t)(row * 128 + kb)));
            }
#pragma unroll
            for (int p = 0; p < 4; p++) {
                int row = warpN * 64 + p * 16 + lrow;
                ldsm4(bH[p], bB + swz128((uint32_t)(row * 128 + kb)));
            }
#pragma unroll
            for (int mt = 0; mt < 4; mt++) {
#pragma unroll
                for (int nt = 0; nt < 8; nt++) {
                    const int p = nt >> 1;
                    const int o = nt & 1;
                    mma_f16(acc[mt][nt], aH[mt], bH[p][o], bH[p][o + 2]);
                }
            }
        }
        if (i + 3 < NCHUNK) issue_loads(i + 3, (i + 3) % NSTAGE);
    }
    __syncthreads();

    // ---- epilogue: regs -> smem -> coalesced out ----
    float* sf = reinterpret_cast<float*>(smem);
    const int g = lane >> 2;
    const int t2 = (lane & 3) * 2;
#pragma unroll
    for (int mt = 0; mt < 4; mt++) {
#pragma unroll
        for (int nt = 0; nt < 8; nt++) {
            int row = warpM * 64 + mt * 16 + g;
            int col = warpN * 64 + nt * 8 + t2;
            sf[row * EPI_STRIDE + col] = acc[mt][nt][0];
            sf[row * EPI_STRIDE + col + 1] = acc[mt][nt][1];
            sf[(row + 8) * EPI_STRIDE + col] = acc[mt][nt][2];
            sf[(row + 8) * EPI_STRIDE + col + 1] = acc[mt][nt][3];
        }
    }
    __syncthreads();

    const int orow = tid;
    const size_t gbase = (size_t)(tm * GBM + orow) * Ntot + (size_t)tn * GBN;
    const size_t rbase = (size_t)(tm * GBM + orow) * DMODEL + (size_t)tn * GBN;
#pragma unroll
    for (int j = 0; j < 32; j++) {
        int col = j * 4;
        float4 v;
        v.x = sf[orow * EPI_STRIDE + col + 0] + bias[tn * GBN + col + 0];
        v.y = sf[orow * EPI_STRIDE + col + 1] + bias[tn * GBN + col + 1];
        v.z = sf[orow * EPI_STRIDE + col + 2] + bias[tn * GBN + col + 2];
        v.w = sf[orow * EPI_STRIDE + col + 3] + bias[tn * GBN + col + 3];
        if (res != nullptr) {
            float4 r4 = *reinterpret_cast<const float4*>(res + rbase + col);
            v.x += r4.x; v.y += r4.y; v.z += r4.z; v.w += r4.w;
        }
        *reinterpret_cast<float4*>(C + gbase + col) = v;
    }
}

// ---------------------------------------------------------------------------
// Block-diagonal attention, 4 queries/warp; writes R1 (fp32) + R1h (fp16)
// ---------------------------------------------------------------------------
__global__ __launch_bounds__(256)
void attn_kernel(const float* __restrict__ QKV, const float* __restrict__ X,
                 float* __restrict__ R1, __half* __restrict__ R1h) {
    const int lane = threadIdx.x & 31;
    const int warp = threadIdx.x >> 5;
    const int q0 = blockIdx.x * 32 + warp * 4;
    const int h = blockIdx.y;
    const size_t hoff = (size_t)h * DHEAD;

    int s0[4], s1[4];
    float qreg[4][16];
#pragma unroll
    for (int i = 0; i < 4; i++) {
        const int q = q0 + i;
        s0[i] = g_seg_start[q];
        s1[i] = g_seg_end[q];
        const float* qrow = QKV + (size_t)q * QKV_N + hoff;
#pragma unroll
        for (int d = 0; d < 16; d++) qreg[i][d] = qrow[lane + 32 * d];
    }
    int jmin = min(min(s0[0], s0[1]), min(s0[2], s0[3]));
    int jmax = max(max(s1[0], s1[1]), max(s1[2], s1[3]));

    float m[4] = {-1e30f, -1e30f, -1e30f, -1e30f};
    float l[4] = {0.f, 0.f, 0.f, 0.f};
    float accv[4][16];
#pragma unroll
    for (int i = 0; i < 4; i++)
#pragma unroll
        for (int d = 0; d < 16; d++) accv[i][d] = 0.0f;

    for (int j = jmin; j < jmax; j++) {
        const float* krow = QKV + (size_t)j * QKV_N + DMODEL + hoff;
        float kr[16];
#pragma unroll
        for (int d = 0; d < 16; d++) kr[d] = krow[lane + 32 * d];

        float s[4] = {0.f, 0.f, 0.f, 0.f};
#pragma unroll
        for (int d = 0; d < 16; d++) {
#pragma unroll
            for (int i = 0; i < 4; i++) s[i] = fmaf(qreg[i][d], kr[d], s[i]);
        }
#pragma unroll
        for (int off = 16; off > 0; off >>= 1) {
#pragma unroll
            for (int i = 0; i < 4; i++) s[i] += __shfl_xor_sync(0xFFFFFFFFu, s[i], off);
        }

        const float* vrow = QKV + (size_t)j * QKV_N + 2 * DMODEL + hoff;
        float vr[16];
#pragma unroll
        for (int d = 0; d < 16; d++) vr[d] = vrow[lane + 32 * d];

#pragma unroll
        for (int i = 0; i < 4; i++) {
            if (j >= s0[i] && j < s1[i]) {
                const float sc = s[i] * ATTN_SCALE;
                const float mn = fmaxf(m[i], sc);
                const float c = __expf(m[i] - mn);
                const float p = __expf(sc - mn);
                l[i] = l[i] * c + p;
#pragma unroll
                for (int d = 0; d < 16; d++)
                    accv[i][d] = fmaf(accv[i][d], c, p * vr[d]);
                m[i] = mn;
            }
        }
    }

#pragma unroll
    for (int i = 0; i < 4; i++) {
        const int q = q0 + i;
        const float inv = 1.0f / l[i];
        const float* xr = X + (size_t)q * DMODEL + hoff;
        float* orow = R1 + (size_t)q * DMODEL + hoff;
        __half* hrow = R1h + (size_t)q * DMODEL + hoff;
#pragma unroll
        for (int d = 0; d < 16; d++) {
            float o = accv[i][d] * inv + xr[lane + 32 * d];
            orow[lane + 32 * d] = o;
            hrow[lane + 32 * d] = __float2half_rn(o);
        }
    }
}

// ---------------------------------------------------------------------------
// kernel_launch
// ---------------------------------------------------------------------------
extern "C" void kernel_launch(void* const* d_in, const int* in_sizes, int n_in,
                              void* d_out, int out_size) {
    const float* X   = (const float*)d_in[0];
    const int*   nr  = (const int*)d_in[1];
    const float* Wq  = (const float*)d_in[2];
    const float* bq  = (const float*)d_in[3];
    const float* Wk  = (const float*)d_in[4];
    const float* bk  = (const float*)d_in[5];
    const float* Wv  = (const float*)d_in[6];
    const float* bv  = (const float*)d_in[7];
    const float* Wfc = (const float*)d_in[8];
    const float* bfc = (const float*)d_in[9];
    float* out = (float*)d_out;

    float *QKV, *R1, *bqkv;
    __half *Xh, *R1h, *Wqkv, *Wf;
    cudaGetSymbolAddress((void**)&QKV, g_QKV);
    cudaGetSymbolAddress((void**)&R1, g_R1);
    cudaGetSymbolAddress((void**)&bqkv, g_bqkv);
    cudaGetSymbolAddress((void**)&Xh, g_Xh);
    cudaGetSymbolAddress((void**)&R1h, g_R1h);
    cudaGetSymbolAddress((void**)&Wqkv, g_Wqkv);
    cudaGetSymbolAddress((void**)&Wf, g_Wf);

    cudaFuncSetAttribute(gemm_f16, cudaFuncAttributeMaxDynamicSharedMemorySize, GEMM_SMEM);

    const int n4 = (NTOK * DMODEL) / 4;

    // prep
    concat_bias<<<(QKV_N + 255) / 256, 256>>>(bq, bk, bv, bqkv);
    convert_h<<<n4 / 256, 256>>>(X, Xh, n4);
    dim3 tgrid3(DMODEL / 32, DMODEL / 32, 3);
    transpose_conv3<<<tgrid3, 256>>>(Wq, Wk, Wv, Wqkv);
    build_seg_kernel<<<1, 256>>>(nr, in_sizes[1]);

    // fused QKV projection
    const int qkv_tiles = NTM * (QKV_N / GBN);
    gemm_f16<<<qkv_tiles, 256, GEMM_SMEM>>>(Xh, Wqkv, bqkv, nullptr, QKV, QKV_N);

    // attention (+ fp16 R1 copy in epilogue)
    dim3 agrid(NTOK / 32, NHEADS);
    attn_kernel<<<agrid, 256>>>(QKV, X, R1, R1h);

    // FC
    dim3 tgridf(DMODEL / 32, DMODEL / 32, 1);
    transpose_conv3<<<tgridf, 256>>>(Wfc, Wfc, Wfc, Wf);
    const int fc_tiles = NTM * (DMODEL / GBN);
    gemm_f16<<<fc_tiles, 256, GEMM_SMEM>>>(R1h, Wf, bfc, R1, out, DMODEL);
}

// round 8
// speedup vs baseline: 6.5444x; 1.2392x over previous
#include <cuda_runtime.h>
#include <cuda_fp16.h>
#include <math.h>
#include <stdint.h>

// ---------------------------------------------------------------------------
// Self_Attention: N=4096 tokens, D=4096, H=8 heads, DH=512
// Round 8: fp16 QKV (GEMM writes half), smem-staged block-shared K/V attention.
// ---------------------------------------------------------------------------
#define NTOK 4096
#define DMODEL 4096
#define NHEADS 8
#define DHEAD 512
#define QKV_N (3 * DMODEL)
#define ATTN_SCALE 0.04419417382415922f  // 1/sqrt(512)

__device__ __half g_QKV[(size_t)NTOK * QKV_N];      // fp16 [token][Q|K|V]
__device__ float g_R1[(size_t)NTOK * DMODEL];
__device__ float g_bqkv[QKV_N];
__device__ __half g_Xh[(size_t)NTOK * DMODEL];
__device__ __half g_R1h[(size_t)NTOK * DMODEL];
__device__ __half g_Wqkv[(size_t)QKV_N * DMODEL];   // [N,K] fp16
__device__ __half g_Wf[(size_t)DMODEL * DMODEL];    // [N,K] fp16
__device__ int g_seg_start[NTOK];
__device__ int g_seg_end[NTOK];

// ---------------------------------------------------------------------------
// PTX helpers
// ---------------------------------------------------------------------------
__device__ __forceinline__ uint32_t smem_u32(const void* p) {
    return (uint32_t)__cvta_generic_to_shared(p);
}
__device__ __forceinline__ uint32_t swz128(uint32_t off) {
    return off ^ ((off >> 3) & 0x70);
}
__device__ __forceinline__ void cp16(uint32_t s, const void* g) {
    asm volatile("cp.async.cg.shared.global [%0], [%1], 16;\n" :: "r"(s), "l"(g));
}
__device__ __forceinline__ void cp_commit() {
    asm volatile("cp.async.commit_group;\n" ::: "memory");
}
__device__ __forceinline__ void cp_wait2() {
    asm volatile("cp.async.wait_group 2;\n" ::: "memory");
}
__device__ __forceinline__ void ldsm4(uint32_t* r, uint32_t addr) {
    asm volatile("ldmatrix.sync.aligned.m8n8.x4.shared.b16 {%0,%1,%2,%3}, [%4];"
                 : "=r"(r[0]), "=r"(r[1]), "=r"(r[2]), "=r"(r[3]) : "r"(addr));
}
__device__ __forceinline__ void mma_f16(float* d, const uint32_t* a,
                                        uint32_t b0, uint32_t b1) {
    asm volatile(
        "mma.sync.aligned.m16n8k16.row.col.f32.f16.f16.f32 "
        "{%0,%1,%2,%3}, {%4,%5,%6,%7}, {%8,%9}, {%0,%1,%2,%3};"
        : "+f"(d[0]), "+f"(d[1]), "+f"(d[2]), "+f"(d[3])
        : "r"(a[0]), "r"(a[1]), "r"(a[2]), "r"(a[3]), "r"(b0), "r"(b1));
}

// ---------------------------------------------------------------------------
// Segment table builder (int32 or int64 num_rels)
// ---------------------------------------------------------------------------
__global__ void build_seg_kernel(const int* __restrict__ nr, int count) {
    __shared__ int starts[160];
    __shared__ int nseg;
    if (count > 128) count = 128;
    if (threadIdx.x == 0) {
        long long s32 = 0;
        for (int i = 0; i < count; i++) s32 += nr[i];
        int is64 = (s32 != (long long)NTOK) ? 1 : 0;
        int acc = 0;
        for (int i = 0; i < count; i++) {
            starts[i] = acc;
            int v = is64 ? nr[2 * i] : nr[i];
            acc += v;
        }
        starts[count] = acc;
        nseg = count;
    }
    __syncthreads();
    int ns = nseg;
    for (int t = threadIdx.x; t < NTOK; t += blockDim.x) {
        int lo = 0;
        while (lo + 1 <= ns && starts[lo + 1] <= t) lo++;
        g_seg_start[t] = starts[lo];
        g_seg_end[t] = starts[lo + 1];
    }
}

// ---------------------------------------------------------------------------
// fp32 -> fp16 convert
// ---------------------------------------------------------------------------
__global__ __launch_bounds__(256)
void convert_h(const float* __restrict__ src, __half* __restrict__ dst, int n4) {
    int i = blockIdx.x * blockDim.x + threadIdx.x;
    if (i >= n4) return;
    float4 v = reinterpret_cast<const float4*>(src)[i];
    __half2 a = __floats2half2_rn(v.x, v.y);
    __half2 b = __floats2half2_rn(v.z, v.w);
    uint2 o;
    o.x = *reinterpret_cast<uint32_t*>(&a);
    o.y = *reinterpret_cast<uint32_t*>(&b);
    reinterpret_cast<uint2*>(dst)[i] = o;
}

// ---------------------------------------------------------------------------
// Weight transpose+convert: grid.z selects Wq/Wk/Wv
// ---------------------------------------------------------------------------
__global__ __launch_bounds__(256)
void transpose_conv3(const float* __restrict__ W0, const float* __restrict__ W1,
                     const float* __restrict__ W2, __half* __restrict__ T) {
    const float* W = (blockIdx.z == 0) ? W0 : (blockIdx.z == 1 ? W1 : W2);
    __half* dst = T + (size_t)blockIdx.z * DMODEL * DMODEL;
    __shared__ float t[32][33];
    int n0 = blockIdx.x * 32;
    int k0 = blockIdx.y * 32;
    int tx = threadIdx.x & 31;
    int ty = threadIdx.x >> 5;
#pragma unroll
    for (int j = 0; j < 32; j += 8)
        t[ty + j][tx] = W[(size_t)(k0 + ty + j) * DMODEL + n0 + tx];
    __syncthreads();
#pragma unroll
    for (int j = 0; j < 32; j += 8) {
        float v = t[tx][ty + j];
        dst[(size_t)(n0 + ty + j) * DMODEL + k0 + tx] = __float2half_rn(v);
    }
}

__global__ void concat_bias(const float* __restrict__ bq, const float* __restrict__ bk,
                            const float* __restrict__ bv, float* __restrict__ dst) {
    int i = blockIdx.x * 256 + threadIdx.x;
    if (i >= QKV_N) return;
    dst[i] = (i < DMODEL) ? bq[i] : (i < 2 * DMODEL ? bk[i - DMODEL] : bv[i - 2 * DMODEL]);
}

// ---------------------------------------------------------------------------
// fp16 HMMA GEMM: C[M,Ntot] = A[M,4096] @ (B[Ntot,4096])^T + bias (+res)
// CTA 256x128, 8 warps (4x2), warp 64x64, BK=64, 4-stage cp.async.
// HALF_OUT: write __half output (QKV); else fp32 (+res).
// ---------------------------------------------------------------------------
#define GBM 256
#define GBN 128
#define GBK 64
#define GK DMODEL
#define NCHUNK (GK / GBK)
#define A_BYTES 32768
#define B_BYTES 16384
#define STAGE_BYTES (A_BYTES + B_BYTES)
#define NSTAGE 4
#define GEMM_SMEM (NSTAGE * STAGE_BYTES)
#define EPI_STRIDE 132
#define NTM (NTOK / GBM)

template <int HALF_OUT>
__global__ __launch_bounds__(256, 1)
void gemm_f16(const __half* __restrict__ Ah, const __half* __restrict__ Bh,
              const float* __restrict__ bias, const float* __restrict__ res,
              void* __restrict__ Cv, int Ntot) {
    extern __shared__ char smem[];
    const uint32_t sb = smem_u32(smem);
    const int tid = threadIdx.x;
    const int wid = tid >> 5;
    const int lane = tid & 31;
    const int warpM = wid >> 1;
    const int warpN = wid & 1;

    const int tm = blockIdx.x % NTM;
    const int tn = blockIdx.x / NTM;

    const char* pAh = (const char*)(Ah + (size_t)tm * GBM * GK);
    const char* pBh = (const char*)(Bh + (size_t)tn * GBN * GK);
    const size_t rowstride = (size_t)GK * 2;

    auto issue_loads = [&](int chunk, int s) {
        const uint32_t base = sb + s * STAGE_BYTES;
        const size_t koff = (size_t)chunk * GBK * 2;
#pragma unroll
        for (int j = 0; j < 8; j++) {
            int u = tid + 256 * j;
            int row = u >> 3;
            int c = (u & 7) * 16;
            uint32_t so = swz128((uint32_t)(row * 128 + c));
            cp16(base + so, pAh + (size_t)row * rowstride + koff + c);
        }
#pragma unroll
        for (int j = 0; j < 4; j++) {
            int u = tid + 256 * j;
            int row = u >> 3;
            int c = (u & 7) * 16;
            uint32_t so = swz128((uint32_t)(row * 128 + c));
            cp16(base + A_BYTES + so, pBh + (size_t)row * rowstride + koff + c);
        }
        cp_commit();
    };

    float acc[4][8][4];
#pragma unroll
    for (int mt = 0; mt < 4; mt++)
#pragma unroll
        for (int nt = 0; nt < 8; nt++)
#pragma unroll
            for (int e = 0; e < 4; e++) acc[mt][nt][e] = 0.0f;

    const int lrow = lane & 15;
    const int lcol = (lane >> 4) * 16;

    issue_loads(0, 0);
    issue_loads(1, 1);
    issue_loads(2, 2);

    for (int i = 0; i < NCHUNK; i++) {
        cp_wait2();
        __syncthreads();
        const int s = i % NSTAGE;
        const uint32_t bA = sb + s * STAGE_BYTES;
        const uint32_t bB = bA + A_BYTES;

#pragma unroll
        for (int ks = 0; ks < 4; ks++) {
            const int kb = ks * 32 + lcol;
            uint32_t aH[4][4], bH[4][4];
#pragma unroll
            for (int mt = 0; mt < 4; mt++) {
                int row = warpM * 64 + mt * 16 + lrow;
                ldsm4(aH[mt], bA + swz128((uint32_t)(row * 128 + kb)));
            }
#pragma unroll
            for (int p = 0; p < 4; p++) {
                int row = warpN * 64 + p * 16 + lrow;
                ldsm4(bH[p], bB + swz128((uint32_t)(row * 128 + kb)));
            }
#pragma unroll
            for (int mt = 0; mt < 4; mt++) {
#pragma unroll
                for (int nt = 0; nt < 8; nt++) {
                    const int p = nt >> 1;
                    const int o = nt & 1;
                    mma_f16(acc[mt][nt], aH[mt], bH[p][o], bH[p][o + 2]);
                }
            }
        }
        if (i + 3 < NCHUNK) issue_loads(i + 3, (i + 3) % NSTAGE);
    }
    __syncthreads();

    // ---- epilogue ----
    float* sf = reinterpret_cast<float*>(smem);
    const int g = lane >> 2;
    const int t2 = (lane & 3) * 2;
#pragma unroll
    for (int mt = 0; mt < 4; mt++) {
#pragma unroll
        for (int nt = 0; nt < 8; nt++) {
            int row = warpM * 64 + mt * 16 + g;
            int col = warpN * 64 + nt * 8 + t2;
            sf[row * EPI_STRIDE + col] = acc[mt][nt][0];
            sf[row * EPI_STRIDE + col + 1] = acc[mt][nt][1];
            sf[(row + 8) * EPI_STRIDE + col] = acc[mt][nt][2];
            sf[(row + 8) * EPI_STRIDE + col + 1] = acc[mt][nt][3];
        }
    }
    __syncthreads();

    const int orow = tid;
    const size_t gbase = (size_t)(tm * GBM + orow) * Ntot + (size_t)tn * GBN;
    const size_t rbase = (size_t)(tm * GBM + orow) * DMODEL + (size_t)tn * GBN;
#pragma unroll
    for (int j = 0; j < 32; j++) {
        int col = j * 4;
        float4 v;
        v.x = sf[orow * EPI_STRIDE + col + 0] + bias[tn * GBN + col + 0];
        v.y = sf[orow * EPI_STRIDE + col + 1] + bias[tn * GBN + col + 1];
        v.z = sf[orow * EPI_STRIDE + col + 2] + bias[tn * GBN + col + 2];
        v.w = sf[orow * EPI_STRIDE + col + 3] + bias[tn * GBN + col + 3];
        if (HALF_OUT) {
            __half2 h0 = __floats2half2_rn(v.x, v.y);
            __half2 h1 = __floats2half2_rn(v.z, v.w);
            uint2 o;
            o.x = *reinterpret_cast<uint32_t*>(&h0);
            o.y = *reinterpret_cast<uint32_t*>(&h1);
            *reinterpret_cast<uint2*>((__half*)Cv + gbase + col) = o;
        } else {
            if (res != nullptr) {
                float4 r4 = *reinterpret_cast<const float4*>(res + rbase + col);
                v.x += r4.x; v.y += r4.y; v.z += r4.z; v.w += r4.w;
            }
            *reinterpret_cast<float4*>((float*)Cv + gbase + col) = v;
        }
    }
}

// ---------------------------------------------------------------------------
// Block-diagonal attention, smem-staged fp16 K/V shared by the block.
// Block = 32 queries x 1 head (8 warps, 4 q/warp). Chunk = 64 KV rows.
// ---------------------------------------------------------------------------
#define ACH 64
#define ATTN_SMEM (2 * ACH * DHEAD * 2)   // K + V chunks, fp16: 131072 B

__global__ __launch_bounds__(256)
void attn_kernel(const __half* __restrict__ QKV, const float* __restrict__ X,
                 float* __restrict__ R1, __half* __restrict__ R1h) {
    extern __shared__ __half skv[];
    __half* Ks = skv;
    __half* Vs = skv + ACH * DHEAD;

    const int tid = threadIdx.x;
    const int lane = tid & 31;
    const int warp = tid >> 5;
    const int q0b = blockIdx.x * 32;
    const int q0 = q0b + warp * 4;
    const int h = blockIdx.y;
    const int hoff = h * DHEAD;

    // block-level KV range (tokens contiguous, segments ordered)
    const int bjmin = g_seg_start[q0b];
    const int bjmax = g_seg_end[q0b + 31];

    int s0[4], s1[4];
    __half2 q2[4][8];
#pragma unroll
    for (int i = 0; i < 4; i++) {
        const int q = q0 + i;
        s0[i] = g_seg_start[q];
        s1[i] = g_seg_end[q];
        const __half2* qrow = (const __half2*)(QKV + (size_t)q * QKV_N + hoff);
#pragma unroll
        for (int d = 0; d < 8; d++) q2[i][d] = qrow[lane + 32 * d];
    }
    const int wjmin = min(min(s0[0], s0[1]), min(s0[2], s0[3]));
    const int wjmax = max(max(s1[0], s1[1]), max(s1[2], s1[3]));

    float m[4] = {-1e30f, -1e30f, -1e30f, -1e30f};
    float l[4] = {0.f, 0.f, 0.f, 0.f};
    float accv[4][16];
#pragma unroll
    for (int i = 0; i < 4; i++)
#pragma unroll
        for (int d = 0; d < 16; d++) accv[i][d] = 0.0f;

    for (int c = bjmin; c < bjmax; c += ACH) {
        const int nrows = min(ACH, bjmax - c);
        __syncthreads();   // previous chunk fully consumed
        // cooperative load: nrows x 64 uint4 each for K and V
        for (int e = tid; e < nrows * 64; e += 256) {
            const int r = e >> 6;
            const int u = e & 63;
            const uint4* krow = (const uint4*)(QKV + (size_t)(c + r) * QKV_N + DMODEL + hoff);
            const uint4* vrow = (const uint4*)(QKV + (size_t)(c + r) * QKV_N + 2 * DMODEL + hoff);
            reinterpret_cast<uint4*>(Ks + r * DHEAD)[u] = krow[u];
            reinterpret_cast<uint4*>(Vs + r * DHEAD)[u] = vrow[u];
        }
        __syncthreads();

        const int j0 = max(c, wjmin);
        const int j1 = min(c + nrows, wjmax);
        for (int j = j0; j < j1; j++) {
            const __half2* kr = (const __half2*)(Ks + (j - c) * DHEAD);
            float s[4] = {0.f, 0.f, 0.f, 0.f};
#pragma unroll
            for (int d = 0; d < 8; d++) {
                const float2 kf = __half22float2(kr[lane + 32 * d]);
#pragma unroll
                for (int i = 0; i < 4; i++) {
                    const float2 qf = __half22float2(q2[i][d]);
                    s[i] = fmaf(qf.x, kf.x, s[i]);
                    s[i] = fmaf(qf.y, kf.y, s[i]);
                }
            }
#pragma unroll
            for (int off = 16; off > 0; off >>= 1) {
#pragma unroll
                for (int i = 0; i < 4; i++)
                    s[i] += __shfl_xor_sync(0xFFFFFFFFu, s[i], off);
            }

            const __half2* vr = (const __half2*)(Vs + (j - c) * DHEAD);
            float2 vf[8];
#pragma unroll
            for (int d = 0; d < 8; d++) vf[d] = __half22float2(vr[lane + 32 * d]);

#pragma unroll
            for (int i = 0; i < 4; i++) {
                if (j >= s0[i] && j < s1[i]) {
                    const float sc = s[i] * ATTN_SCALE;
                    const float mn = fmaxf(m[i], sc);
                    const float ce = __expf(m[i] - mn);
                    const float p = __expf(sc - mn);
                    l[i] = l[i] * ce + p;
#pragma unroll
                    for (int d = 0; d < 8; d++) {
                        accv[i][2 * d] = fmaf(accv[i][2 * d], ce, p * vf[d].x);
                        accv[i][2 * d + 1] = fmaf(accv[i][2 * d + 1], ce, p * vf[d].y);
                    }
                    m[i] = mn;
                }
            }
        }
    }

#pragma unroll
    for (int i = 0; i < 4; i++) {
        const int q = q0 + i;
        const float inv = 1.0f / l[i];
        const float2* xr = (const float2*)(X + (size_t)q * DMODEL + hoff);
        float2* orow = (float2*)(R1 + (size_t)q * DMODEL + hoff);
        __half2* hrow = (__half2*)(R1h + (size_t)q * DMODEL + hoff);
#pragma unroll
        for (int d = 0; d < 8; d++) {
            const float2 x2 = xr[lane + 32 * d];
            float2 o;
            o.x = accv[i][2 * d] * inv + x2.x;
            o.y = accv[i][2 * d + 1] * inv + x2.y;
            orow[lane + 32 * d] = o;
            hrow[lane + 32 * d] = __floats2half2_rn(o.x, o.y);
        }
    }
}

// ---------------------------------------------------------------------------
// kernel_launch
// ---------------------------------------------------------------------------
extern "C" void kernel_launch(void* const* d_in, const int* in_sizes, int n_in,
                              void* d_out, int out_size) {
    const float* X   = (const float*)d_in[0];
    const int*   nr  = (const int*)d_in[1];
    const float* Wq  = (const float*)d_in[2];
    const float* bq  = (const float*)d_in[3];
    const float* Wk  = (const float*)d_in[4];
    const float* bk  = (const float*)d_in[5];
    const float* Wv  = (const float*)d_in[6];
    const float* bv  = (const float*)d_in[7];
    const float* Wfc = (const float*)d_in[8];
    const float* bfc = (const float*)d_in[9];
    float* out = (float*)d_out;

    float *R1, *bqkv;
    __half *QKV, *Xh, *R1h, *Wqkv, *Wf;
    cudaGetSymbolAddress((void**)&QKV, g_QKV);
    cudaGetSymbolAddress((void**)&R1, g_R1);
    cudaGetSymbolAddress((void**)&bqkv, g_bqkv);
    cudaGetSymbolAddress((void**)&Xh, g_Xh);
    cudaGetSymbolAddress((void**)&R1h, g_R1h);
    cudaGetSymbolAddress((void**)&Wqkv, g_Wqkv);
    cudaGetSymbolAddress((void**)&Wf, g_Wf);

    cudaFuncSetAttribute(gemm_f16<0>, cudaFuncAttributeMaxDynamicSharedMemorySize, GEMM_SMEM);
    cudaFuncSetAttribute(gemm_f16<1>, cudaFuncAttributeMaxDynamicSharedMemorySize, GEMM_SMEM);
    cudaFuncSetAttribute(attn_kernel, cudaFuncAttributeMaxDynamicSharedMemorySize, ATTN_SMEM);

    const int n4 = (NTOK * DMODEL) / 4;

    // prep
    concat_bias<<<(QKV_N + 255) / 256, 256>>>(bq, bk, bv, bqkv);
    convert_h<<<n4 / 256, 256>>>(X, Xh, n4);
    dim3 tgrid3(DMODEL / 32, DMODEL / 32, 3);
    transpose_conv3<<<tgrid3, 256>>>(Wq, Wk, Wv, Wqkv);
    build_seg_kernel<<<1, 256>>>(nr, in_sizes[1]);

    // fused QKV projection -> fp16
    const int qkv_tiles = NTM * (QKV_N / GBN);
    gemm_f16<1><<<qkv_tiles, 256, GEMM_SMEM>>>(Xh, Wqkv, bqkv, nullptr, QKV, QKV_N);

    // attention (+ fp16 R1 copy in epilogue)
    dim3 agrid(NTOK / 32, NHEADS);
    attn_kernel<<<agrid, 256, ATTN_SMEM>>>(QKV, X, R1, R1h);

    // FC
    dim3 tgridf(DMODEL / 32, DMODEL / 32, 1);
    transpose_conv3<<<tgridf, 256>>>(Wfc, Wfc, Wfc, Wf);
    const int fc_tiles = NTM * (DMODEL / GBN);
    gemm_f16<0><<<fc_tiles, 256, GEMM_SMEM>>>(R1h, Wf, bfc, R1, out, DMODEL);
}

// round 9
// speedup vs baseline: 6.6869x; 1.0218x over previous
#include <cuda_runtime.h>
#include <cuda_fp16.h>
#include <math.h>
#include <stdint.h>

// ---------------------------------------------------------------------------
// Self_Attention: N=4096 tokens, D=4096, H=8 heads, DH=512
// Round 9: BK=128 2-stage GEMM pipeline; cp.async double-buffered attention;
//          single z=4 weight transpose.
// ---------------------------------------------------------------------------
#define NTOK 4096
#define DMODEL 4096
#define NHEADS 8
#define DHEAD 512
#define QKV_N (3 * DMODEL)
#define ATTN_SCALE 0.04419417382415922f  // 1/sqrt(512)

__device__ __half g_QKV[(size_t)NTOK * QKV_N];      // fp16 [token][Q|K|V]
__device__ float g_R1[(size_t)NTOK * DMODEL];
__device__ float g_bqkv[QKV_N];
__device__ __half g_Xh[(size_t)NTOK * DMODEL];
__device__ __half g_R1h[(size_t)NTOK * DMODEL];
__device__ __half g_W[(size_t)4 * DMODEL * DMODEL]; // [Wq|Wk|Wv|Wfc], each [N,K] fp16
__device__ int g_seg_start[NTOK];
__device__ int g_seg_end[NTOK];

// ---------------------------------------------------------------------------
// PTX helpers
// ---------------------------------------------------------------------------
__device__ __forceinline__ uint32_t smem_u32(const void* p) {
    return (uint32_t)__cvta_generic_to_shared(p);
}
__device__ __forceinline__ uint32_t swz128(uint32_t off) {
    return off ^ ((off >> 3) & 0x70);
}
__device__ __forceinline__ void cp16(uint32_t s, const void* g) {
    asm volatile("cp.async.cg.shared.global [%0], [%1], 16;\n" :: "r"(s), "l"(g));
}
__device__ __forceinline__ void cp_commit() {
    asm volatile("cp.async.commit_group;\n" ::: "memory");
}
__device__ __forceinline__ void cp_wait0() {
    asm volatile("cp.async.wait_group 0;\n" ::: "memory");
}
__device__ __forceinline__ void cp_wait1() {
    asm volatile("cp.async.wait_group 1;\n" ::: "memory");
}
__device__ __forceinline__ void ldsm4(uint32_t* r, uint32_t addr) {
    asm volatile("ldmatrix.sync.aligned.m8n8.x4.shared.b16 {%0,%1,%2,%3}, [%4];"
                 : "=r"(r[0]), "=r"(r[1]), "=r"(r[2]), "=r"(r[3]) : "r"(addr));
}
__device__ __forceinline__ void mma_f16(float* d, const uint32_t* a,
                                        uint32_t b0, uint32_t b1) {
    asm volatile(
        "mma.sync.aligned.m16n8k16.row.col.f32.f16.f16.f32 "
        "{%0,%1,%2,%3}, {%4,%5,%6,%7}, {%8,%9}, {%0,%1,%2,%3};"
        : "+f"(d[0]), "+f"(d[1]), "+f"(d[2]), "+f"(d[3])
        : "r"(a[0]), "r"(a[1]), "r"(a[2]), "r"(a[3]), "r"(b0), "r"(b1));
}

// ---------------------------------------------------------------------------
// Segment table builder (int32 or int64 num_rels)
// ---------------------------------------------------------------------------
__global__ void build_seg_kernel(const int* __restrict__ nr, int count) {
    __shared__ int starts[160];
    __shared__ int nseg;
    if (count > 128) count = 128;
    if (threadIdx.x == 0) {
        long long s32 = 0;
        for (int i = 0; i < count; i++) s32 += nr[i];
        int is64 = (s32 != (long long)NTOK) ? 1 : 0;
        int acc = 0;
        for (int i = 0; i < count; i++) {
            starts[i] = acc;
            int v = is64 ? nr[2 * i] : nr[i];
            acc += v;
        }
        starts[count] = acc;
        nseg = count;
    }
    __syncthreads();
    int ns = nseg;
    for (int t = threadIdx.x; t < NTOK; t += blockDim.x) {
        int lo = 0;
        while (lo + 1 <= ns && starts[lo + 1] <= t) lo++;
        g_seg_start[t] = starts[lo];
        g_seg_end[t] = starts[lo + 1];
    }
}

// ---------------------------------------------------------------------------
// fp32 -> fp16 convert
// ---------------------------------------------------------------------------
__global__ __launch_bounds__(256)
void convert_h(const float* __restrict__ src, __half* __restrict__ dst, int n4) {
    int i = blockIdx.x * blockDim.x + threadIdx.x;
    if (i >= n4) return;
    float4 v = reinterpret_cast<const float4*>(src)[i];
    __half2 a = __floats2half2_rn(v.x, v.y);
    __half2 b = __floats2half2_rn(v.z, v.w);
    uint2 o;
    o.x = *reinterpret_cast<uint32_t*>(&a);
    o.y = *reinterpret_cast<uint32_t*>(&b);
    reinterpret_cast<uint2*>(dst)[i] = o;
}

// ---------------------------------------------------------------------------
// Weight transpose+convert: grid.z=4 selects Wq/Wk/Wv/Wfc
// ---------------------------------------------------------------------------
__global__ __launch_bounds__(256)
void transpose_conv4(const float* __restrict__ W0, const float* __restrict__ W1,
                     const float* __restrict__ W2, const float* __restrict__ W3,
                     __half* __restrict__ T) {
    const float* W = (blockIdx.z == 0) ? W0 : (blockIdx.z == 1 ? W1
                     : (blockIdx.z == 2 ? W2 : W3));
    __half* dst = T + (size_t)blockIdx.z * DMODEL * DMODEL;
    __shared__ float t[32][33];
    int n0 = blockIdx.x * 32;
    int k0 = blockIdx.y * 32;
    int tx = threadIdx.x & 31;
    int ty = threadIdx.x >> 5;
#pragma unroll
    for (int j = 0; j < 32; j += 8)
        t[ty + j][tx] = W[(size_t)(k0 + ty + j) * DMODEL + n0 + tx];
    __syncthreads();
#pragma unroll
    for (int j = 0; j < 32; j += 8) {
        float v = t[tx][ty + j];
        dst[(size_t)(n0 + ty + j) * DMODEL + k0 + tx] = __float2half_rn(v);
    }
}

__global__ void concat_bias(const float* __restrict__ bq, const float* __restrict__ bk,
                            const float* __restrict__ bv, float* __restrict__ dst) {
    int i = blockIdx.x * 256 + threadIdx.x;
    if (i >= QKV_N) return;
    dst[i] = (i < DMODEL) ? bq[i] : (i < 2 * DMODEL ? bk[i - DMODEL] : bv[i - 2 * DMODEL]);
}

// ---------------------------------------------------------------------------
// fp16 HMMA GEMM: C[M,Ntot] = A[M,4096] @ (B[Ntot,4096])^T + bias (+res)
// CTA 256x128, 8 warps (4x2), warp 64x64, BK=128 (2x64 sub-chunks), 2-stage.
// ---------------------------------------------------------------------------
#define GBM 256
#define GBN 128
#define GBK 128
#define GK DMODEL
#define NCHUNK (GK / GBK)          // 32
#define A_SUB 32768                // 256 rows x 128B per 64-half sub-chunk
#define B_SUB 16384                // 128 rows x 128B
#define STAGE_BYTES (2 * A_SUB + 2 * B_SUB)   // 98304
#define NSTAGE 2
#define GEMM_SMEM (NSTAGE * STAGE_BYTES)      // 196608
#define EPI_STRIDE 132
#define NTM (NTOK / GBM)

template <int HALF_OUT>
__global__ __launch_bounds__(256, 1)
void gemm_f16(const __half* __restrict__ Ah, const __half* __restrict__ Bh,
              const float* __restrict__ bias, const float* __restrict__ res,
              void* __restrict__ Cv, int Ntot) {
    extern __shared__ char smem[];
    const uint32_t sb = smem_u32(smem);
    const int tid = threadIdx.x;
    const int wid = tid >> 5;
    const int lane = tid & 31;
    const int warpM = wid >> 1;
    const int warpN = wid & 1;

    const int tm = blockIdx.x % NTM;
    const int tn = blockIdx.x / NTM;

    const char* pAh = (const char*)(Ah + (size_t)tm * GBM * GK);
    const char* pBh = (const char*)(Bh + (size_t)tn * GBN * GK);
    const size_t rowstride = (size_t)GK * 2;   // 8192 B

    auto issue_loads = [&](int chunk, int s) {
        const uint32_t base = sb + s * STAGE_BYTES;
        const size_t koff = (size_t)chunk * GBK * 2;   // 256 B per chunk
#pragma unroll
        for (int sub = 0; sub < 2; sub++) {
            const uint32_t ab = base + sub * A_SUB;
            const uint32_t bb = base + 2 * A_SUB + sub * B_SUB;
            const size_t ko = koff + sub * 128;
#pragma unroll
            for (int j = 0; j < 8; j++) {
                int u = tid + 256 * j;
                int row = u >> 3;
                int c = (u & 7) * 16;
                uint32_t so = swz128((uint32_t)(row * 128 + c));
                cp16(ab + so, pAh + (size_t)row * rowstride + ko + c);
            }
#pragma unroll
            for (int j = 0; j < 4; j++) {
                int u = tid + 256 * j;
                int row = u >> 3;
                int c = (u & 7) * 16;
                uint32_t so = swz128((uint32_t)(row * 128 + c));
                cp16(bb + so, pBh + (size_t)row * rowstride + ko + c);
            }
        }
        cp_commit();
    };

    float acc[4][8][4];
#pragma unroll
    for (int mt = 0; mt < 4; mt++)
#pragma unroll
        for (int nt = 0; nt < 8; nt++)
#pragma unroll
            for (int e = 0; e < 4; e++) acc[mt][nt][e] = 0.0f;

    const int lrow = lane & 15;
    const int lcol = (lane >> 4) * 16;

    issue_loads(0, 0);
    issue_loads(1, 1);

    for (int i = 0; i < NCHUNK; i++) {
        cp_wait1();                 // chunk i resident
        __syncthreads();
        const int s = i & 1;
        const uint32_t base = sb + s * STAGE_BYTES;

#pragma unroll
        for (int ks = 0; ks < 8; ks++) {
            const int sub = ks >> 2;
            const int kb = (ks & 3) * 32 + lcol;
            const uint32_t bA = base + sub * A_SUB;
            const uint32_t bB = base + 2 * A_SUB + sub * B_SUB;
            uint32_t aH[4][4], bH[4][4];
#pragma unroll
            for (int mt = 0; mt < 4; mt++) {
                int row = warpM * 64 + mt * 16 + lrow;
                ldsm4(aH[mt], bA + swz128((uint32_t)(row * 128 + kb)));
            }
#pragma unroll
            for (int p = 0; p < 4; p++) {
                int row = warpN * 64 + p * 16 + lrow;
                ldsm4(bH[p], bB + swz128((uint32_t)(row * 128 + kb)));
            }
#pragma unroll
            for (int mt = 0; mt < 4; mt++) {
#pragma unroll
                for (int nt = 0; nt < 8; nt++) {
                    const int p = nt >> 1;
                    const int o = nt & 1;
                    mma_f16(acc[mt][nt], aH[mt], bH[p][o], bH[p][o + 2]);
                }
            }
        }
        __syncthreads();            // done reading stage s
        if (i + 2 < NCHUNK) issue_loads(i + 2, s);
    }
    __syncthreads();

    // ---- epilogue ----
    float* sf = reinterpret_cast<float*>(smem);
    const int g = lane >> 2;
    const int t2 = (lane & 3) * 2;
#pragma unroll
    for (int mt = 0; mt < 4; mt++) {
#pragma unroll
        for (int nt = 0; nt < 8; nt++) {
            int row = warpM * 64 + mt * 16 + g;
            int col = warpN * 64 + nt * 8 + t2;
            sf[row * EPI_STRIDE + col] = acc[mt][nt][0];
            sf[row * EPI_STRIDE + col + 1] = acc[mt][nt][1];
            sf[(row + 8) * EPI_STRIDE + col] = acc[mt][nt][2];
            sf[(row + 8) * EPI_STRIDE + col + 1] = acc[mt][nt][3];
        }
    }
    __syncthreads();

    const int orow = tid;
    const size_t gbase = (size_t)(tm * GBM + orow) * Ntot + (size_t)tn * GBN;
    const size_t rbase = (size_t)(tm * GBM + orow) * DMODEL + (size_t)tn * GBN;
#pragma unroll
    for (int j = 0; j < 32; j++) {
        int col = j * 4;
        float4 v;
        v.x = sf[orow * EPI_STRIDE + col + 0] + bias[tn * GBN + col + 0];
        v.y = sf[orow * EPI_STRIDE + col + 1] + bias[tn * GBN + col + 1];
        v.z = sf[orow * EPI_STRIDE + col + 2] + bias[tn * GBN + col + 2];
        v.w = sf[orow * EPI_STRIDE + col + 3] + bias[tn * GBN + col + 3];
        if (HALF_OUT) {
            __half2 h0 = __floats2half2_rn(v.x, v.y);
            __half2 h1 = __floats2half2_rn(v.z, v.w);
            uint2 o;
            o.x = *reinterpret_cast<uint32_t*>(&h0);
            o.y = *reinterpret_cast<uint32_t*>(&h1);
            *reinterpret_cast<uint2*>((__half*)Cv + gbase + col) = o;
        } else {
            if (res != nullptr) {
                float4 r4 = *reinterpret_cast<const float4*>(res + rbase + col);
                v.x += r4.x; v.y += r4.y; v.z += r4.z; v.w += r4.w;
            }
            *reinterpret_cast<float4*>((float*)Cv + gbase + col) = v;
        }
    }
}

// ---------------------------------------------------------------------------
// Block-diagonal attention, cp.async double-buffered smem K/V.
// Block = 32 queries x 1 head (8 warps, 4 q/warp). Chunk = 32 KV rows.
// ---------------------------------------------------------------------------
#define ACH 32
#define KV_BYTES (ACH * DHEAD * 2)            // 32 KB per matrix per buffer
#define ABUF_BYTES (2 * KV_BYTES)             // K + V = 64 KB
#define ATTN_SMEM (2 * ABUF_BYTES)            // double buffer = 128 KB

__global__ __launch_bounds__(256)
void attn_kernel(const __half* __restrict__ QKV, const float* __restrict__ X,
                 float* __restrict__ R1, __half* __restrict__ R1h) {
    extern __shared__ char smem[];
    const uint32_t sb = smem_u32(smem);

    const int tid = threadIdx.x;
    const int lane = tid & 31;
    const int warp = tid >> 5;
    const int q0b = blockIdx.x * 32;
    const int q0 = q0b + warp * 4;
    const int h = blockIdx.y;
    const int hoff = h * DHEAD;

    const int bjmin = g_seg_start[q0b];
    const int bjmax = g_seg_end[q0b + 31];
    const int nch = (bjmax - bjmin + ACH - 1) / ACH;

    int s0[4], s1[4];
    __half2 q2[4][8];
#pragma unroll
    for (int i = 0; i < 4; i++) {
        const int q = q0 + i;
        s0[i] = g_seg_start[q];
        s1[i] = g_seg_end[q];
        const __half2* qrow = (const __half2*)(QKV + (size_t)q * QKV_N + hoff);
#pragma unroll
        for (int d = 0; d < 8; d++) q2[i][d] = qrow[lane + 32 * d];
    }
    const int wjmin = min(min(s0[0], s0[1]), min(s0[2], s0[3]));
    const int wjmax = max(max(s1[0], s1[1]), max(s1[2], s1[3]));

    float m[4] = {-1e30f, -1e30f, -1e30f, -1e30f};
    float l[4] = {0.f, 0.f, 0.f, 0.f};
    float accv[4][16];
#pragma unroll
    for (int i = 0; i < 4; i++)
#pragma unroll
        for (int d = 0; d < 16; d++) accv[i][d] = 0.0f;

    // cp.async chunk loader: 2048 x 16B units for K and V (16 per thread)
    auto load_chunk = [&](int c, int buf) {
        const uint32_t kb = sb + buf * ABUF_BYTES;
        const uint32_t vb = kb + KV_BYTES;
#pragma unroll
        for (int j = 0; j < 8; j++) {
            int e = tid + 256 * j;
            int r = e >> 6;
            int u = (e & 63) * 16;
            int rc = min(c + r, bjmax - 1);
            const char* kg = (const char*)(QKV + (size_t)rc * QKV_N + DMODEL + hoff) + u;
            const char* vg = (const char*)(QKV + (size_t)rc * QKV_N + 2 * DMODEL + hoff) + u;
            cp16(kb + r * 1024 + u, kg);
            cp16(vb + r * 1024 + u, vg);
        }
        cp_commit();
    };

    load_chunk(bjmin, 0);
    if (nch > 1) load_chunk(bjmin + ACH, 1);

    for (int ci = 0; ci < nch; ci++) {
        const int c = bjmin + ci * ACH;
        const int nrows = min(ACH, bjmax - c);
        if (ci + 1 < nch) cp_wait1(); else cp_wait0();
        __syncthreads();

        const int buf = ci & 1;
        const __half* Ks = (const __half*)(smem + buf * ABUF_BYTES);
        const __half* Vs = (const __half*)(smem + buf * ABUF_BYTES + KV_BYTES);

        const int j0 = max(c, wjmin);
        const int j1 = min(c + nrows, wjmax);
        for (int j = j0; j < j1; j++) {
            const __half2* kr = (const __half2*)(Ks + (j - c) * DHEAD);
            float s[4] = {0.f, 0.f, 0.f, 0.f};
#pragma unroll
            for (int d = 0; d < 8; d++) {
                const float2 kf = __half22float2(kr[lane + 32 * d]);
#pragma unroll
                for (int i = 0; i < 4; i++) {
                    const float2 qf = __half22float2(q2[i][d]);
                    s[i] = fmaf(qf.x, kf.x, s[i]);
                    s[i] = fmaf(qf.y, kf.y, s[i]);
                }
            }
#pragma unroll
            for (int off = 16; off > 0; off >>= 1) {
#pragma unroll
                for (int i = 0; i < 4; i++)
                    s[i] += __shfl_xor_sync(0xFFFFFFFFu, s[i], off);
            }

            const __half2* vr = (const __half2*)(Vs + (j - c) * DHEAD);
            float2 vf[8];
#pragma unroll
            for (int d = 0; d < 8; d++) vf[d] = __half22float2(vr[lane + 32 * d]);

#pragma unroll
            for (int i = 0; i < 4; i++) {
                if (j >= s0[i] && j < s1[i]) {
                    const float sc = s[i] * ATTN_SCALE;
                    const float mn = fmaxf(m[i], sc);
                    const float ce = __expf(m[i] - mn);
                    const float p = __expf(sc - mn);
                    l[i] = l[i] * ce + p;
#pragma unroll
                    for (int d = 0; d < 8; d++) {
                        accv[i][2 * d] = fmaf(accv[i][2 * d], ce, p * vf[d].x);
                        accv[i][2 * d + 1] = fmaf(accv[i][2 * d + 1], ce, p * vf[d].y);
                    }
                    m[i] = mn;
                }
            }
        }
        __syncthreads();   // all warps done with buf before it is refilled
        if (ci + 2 < nch) load_chunk(bjmin + (ci + 2) * ACH, buf);
    }

#pragma unroll
    for (int i = 0; i < 4; i++) {
        const int q = q0 + i;
        const float inv = 1.0f / l[i];
        const float2* xr = (const float2*)(X + (size_t)q * DMODEL + hoff);
        float2* orow = (float2*)(R1 + (size_t)q * DMODEL + hoff);
        __half2* hrow = (__half2*)(R1h + (size_t)q * DMODEL + hoff);
#pragma unroll
        for (int d = 0; d < 8; d++) {
            const float2 x2 = xr[lane + 32 * d];
            float2 o;
            o.x = accv[i][2 * d] * inv + x2.x;
            o.y = accv[i][2 * d + 1] * inv + x2.y;
            orow[lane + 32 * d] = o;
            hrow[lane + 32 * d] = __floats2half2_rn(o.x, o.y);
        }
    }
}

// ---------------------------------------------------------------------------
// kernel_launch
// ---------------------------------------------------------------------------
extern "C" void kernel_launch(void* const* d_in, const int* in_sizes, int n_in,
                              void* d_out, int out_size) {
    const float* X   = (const float*)d_in[0];
    const int*   nr  = (const int*)d_in[1];
    const float* Wq  = (const float*)d_in[2];
    const float* bq  = (const float*)d_in[3];
    const float* Wk  = (const float*)d_in[4];
    const float* bk  = (const float*)d_in[5];
    const float* Wv  = (const float*)d_in[6];
    const float* bv  = (const float*)d_in[7];
    const float* Wfc = (const float*)d_in[8];
    const float* bfc = (const float*)d_in[9];
    float* out = (float*)d_out;

    float *R1, *bqkv;
    __half *QKV, *Xh, *R1h, *W;
    cudaGetSymbolAddress((void**)&QKV, g_QKV);
    cudaGetSymbolAddress((void**)&R1, g_R1);
    cudaGetSymbolAddress((void**)&bqkv, g_bqkv);
    cudaGetSymbolAddress((void**)&Xh, g_Xh);
    cudaGetSymbolAddress((void**)&R1h, g_R1h);
    cudaGetSymbolAddress((void**)&W, g_W);

    cudaFuncSetAttribute(gemm_f16<0>, cudaFuncAttributeMaxDynamicSharedMemorySize, GEMM_SMEM);
    cudaFuncSetAttribute(gemm_f16<1>, cudaFuncAttributeMaxDynamicSharedMemorySize, GEMM_SMEM);
    cudaFuncSetAttribute(attn_kernel, cudaFuncAttributeMaxDynamicSharedMemorySize, ATTN_SMEM);

    const int n4 = (NTOK * DMODEL) / 4;

    // prep
    concat_bias<<<(QKV_N + 255) / 256, 256>>>(bq, bk, bv, bqkv);
    convert_h<<<n4 / 256, 256>>>(X, Xh, n4);
    dim3 tgrid4(DMODEL / 32, DMODEL / 32, 4);
    transpose_conv4<<<tgrid4, 256>>>(Wq, Wk, Wv, Wfc, W);
    build_seg_kernel<<<1, 256>>>(nr, in_sizes[1]);

    // fused QKV projection -> fp16
    const int qkv_tiles = NTM * (QKV_N / GBN);
    gemm_f16<1><<<qkv_tiles, 256, GEMM_SMEM>>>(Xh, W, bqkv, nullptr, QKV, QKV_N);

    // attention (+ fp16 R1 copy in epilogue)
    dim3 agrid(NTOK / 32, NHEADS);
    attn_kernel<<<agrid, 256, ATTN_SMEM>>>(QKV, X, R1, R1h);

    // FC: out = R1 + R1 @ Wfc + bfc
    const int fc_tiles = NTM * (DMODEL / GBN);
    gemm_f16<0><<<fc_tiles, 256, GEMM_SMEM>>>(R1h, W + (size_t)3 * DMODEL * DMODEL,
                                              bfc, R1, out, DMODEL);
}

// round 10
// speedup vs baseline: 6.7331x; 1.0069x over previous
#include <cuda_runtime.h>
#include <cuda_fp16.h>
#include <math.h>
#include <stdint.h>

// ---------------------------------------------------------------------------
// Self_Attention: N=4096 tokens, D=4096, H=8 heads, DH=512
// Round 10: persistent GEMM (no wave quantization), fp16-only R1,
//           fixed last-chunk cp.async wait, parallel build_seg.
// ---------------------------------------------------------------------------
#define NTOK 4096
#define DMODEL 4096
#define NHEADS 8
#define DHEAD 512
#define QKV_N (3 * DMODEL)
#define ATTN_SCALE 0.04419417382415922f  // 1/sqrt(512)

__device__ __half g_QKV[(size_t)NTOK * QKV_N];      // fp16 [token][Q|K|V]
__device__ float g_bqkv[QKV_N];
__device__ __half g_Xh[(size_t)NTOK * DMODEL];
__device__ __half g_R1h[(size_t)NTOK * DMODEL];
__device__ __half g_W[(size_t)4 * DMODEL * DMODEL]; // [Wq|Wk|Wv|Wfc], each [N,K] fp16
__device__ int g_seg_start[NTOK];
__device__ int g_seg_end[NTOK];

// ---------------------------------------------------------------------------
// PTX helpers
// ---------------------------------------------------------------------------
__device__ __forceinline__ uint32_t smem_u32(const void* p) {
    return (uint32_t)__cvta_generic_to_shared(p);
}
__device__ __forceinline__ uint32_t swz128(uint32_t off) {
    return off ^ ((off >> 3) & 0x70);
}
__device__ __forceinline__ void cp16(uint32_t s, const void* g) {
    asm volatile("cp.async.cg.shared.global [%0], [%1], 16;\n" :: "r"(s), "l"(g));
}
__device__ __forceinline__ void cp_commit() {
    asm volatile("cp.async.commit_group;\n" ::: "memory");
}
__device__ __forceinline__ void cp_wait0() {
    asm volatile("cp.async.wait_group 0;\n" ::: "memory");
}
__device__ __forceinline__ void cp_wait1() {
    asm volatile("cp.async.wait_group 1;\n" ::: "memory");
}
__device__ __forceinline__ void ldsm4(uint32_t* r, uint32_t addr) {
    asm volatile("ldmatrix.sync.aligned.m8n8.x4.shared.b16 {%0,%1,%2,%3}, [%4];"
                 : "=r"(r[0]), "=r"(r[1]), "=r"(r[2]), "=r"(r[3]) : "r"(addr));
}
__device__ __forceinline__ void mma_f16(float* d, const uint32_t* a,
                                        uint32_t b0, uint32_t b1) {
    asm volatile(
        "mma.sync.aligned.m16n8k16.row.col.f32.f16.f16.f32 "
        "{%0,%1,%2,%3}, {%4,%5,%6,%7}, {%8,%9}, {%0,%1,%2,%3};"
        : "+f"(d[0]), "+f"(d[1]), "+f"(d[2]), "+f"(d[3])
        : "r"(a[0]), "r"(a[1]), "r"(a[2]), "r"(a[3]), "r"(b0), "r"(b1));
}

// ---------------------------------------------------------------------------
// Segment table builder: 16 blocks x 256 threads, binary search per token.
// ---------------------------------------------------------------------------
__global__ void build_seg_kernel(const int* __restrict__ nr, int count) {
    __shared__ int starts[160];
    __shared__ int nseg;
    if (count > 128) count = 128;
    if (threadIdx.x == 0) {
        long long s32 = 0;
        for (int i = 0; i < count; i++) s32 += nr[i];
        int is64 = (s32 != (long long)NTOK) ? 1 : 0;
        int acc = 0;
        for (int i = 0; i < count; i++) {
            starts[i] = acc;
            acc += is64 ? nr[2 * i] : nr[i];
        }
        starts[count] = acc;
        nseg = count;
    }
    __syncthreads();
    const int ns = nseg;
    const int t = blockIdx.x * 256 + threadIdx.x;
    if (t >= NTOK) return;
    // binary search: largest lo with starts[lo] <= t  (strictly increasing OK;
    // equal starts from zero-length segments resolve to the last one <= t,
    // and tokens never fall in zero-length segments)
    int lo = 0, hi = ns;   // invariant: starts[lo] <= t < starts[hi]
    while (hi - lo > 1) {
        int mid = (lo + hi) >> 1;
        if (starts[mid] <= t) lo = mid; else hi = mid;
    }
    g_seg_start[t] = starts[lo];
    g_seg_end[t] = starts[hi == lo + 1 ? hi : lo + 1];
}

// ---------------------------------------------------------------------------
// fp32 -> fp16 convert
// ---------------------------------------------------------------------------
__global__ __launch_bounds__(256)
void convert_h(const float* __restrict__ src, __half* __restrict__ dst, int n4) {
    int i = blockIdx.x * blockDim.x + threadIdx.x;
    if (i >= n4) return;
    float4 v = reinterpret_cast<const float4*>(src)[i];
    __half2 a = __floats2half2_rn(v.x, v.y);
    __half2 b = __floats2half2_rn(v.z, v.w);
    uint2 o;
    o.x = *reinterpret_cast<uint32_t*>(&a);
    o.y = *reinterpret_cast<uint32_t*>(&b);
    reinterpret_cast<uint2*>(dst)[i] = o;
}

// ---------------------------------------------------------------------------
// Weight transpose+convert: grid.z=4 selects Wq/Wk/Wv/Wfc
// ---------------------------------------------------------------------------
__global__ __launch_bounds__(256)
void transpose_conv4(const float* __restrict__ W0, const float* __restrict__ W1,
                     const float* __restrict__ W2, const float* __restrict__ W3,
                     __half* __restrict__ T) {
    const float* W = (blockIdx.z == 0) ? W0 : (blockIdx.z == 1 ? W1
                     : (blockIdx.z == 2 ? W2 : W3));
    __half* dst = T + (size_t)blockIdx.z * DMODEL * DMODEL;
    __shared__ float t[32][33];
    int n0 = blockIdx.x * 32;
    int k0 = blockIdx.y * 32;
    int tx = threadIdx.x & 31;
    int ty = threadIdx.x >> 5;
#pragma unroll
    for (int j = 0; j < 32; j += 8)
        t[ty + j][tx] = W[(size_t)(k0 + ty + j) * DMODEL + n0 + tx];
    __syncthreads();
#pragma unroll
    for (int j = 0; j < 32; j += 8) {
        float v = t[tx][ty + j];
        dst[(size_t)(n0 + ty + j) * DMODEL + k0 + tx] = __float2half_rn(v);
    }
}

__global__ void concat_bias(const float* __restrict__ bq, const float* __restrict__ bk,
                            const float* __restrict__ bv, float* __restrict__ dst) {
    int i = blockIdx.x * 256 + threadIdx.x;
    if (i >= QKV_N) return;
    dst[i] = (i < DMODEL) ? bq[i] : (i < 2 * DMODEL ? bk[i - DMODEL] : bv[i - 2 * DMODEL]);
}

// ---------------------------------------------------------------------------
// Persistent fp16 HMMA GEMM: C[M,Ntot] = A @ B^T + bias (+ res fp16)
// CTA 256x128, 8 warps (4x2), warp 64x64, BK=128 (2x64 sub), 2-stage.
// grid = #SMs; each CTA strides over tiles.
// ---------------------------------------------------------------------------
#define GBM 256
#define GBN 128
#define GBK 128
#define GK DMODEL
#define NCHUNK (GK / GBK)          // 32
#define A_SUB 32768
#define B_SUB 16384
#define STAGE_BYTES (2 * A_SUB + 2 * B_SUB)   // 98304
#define GEMM_SMEM (2 * STAGE_BYTES)           // 196608
#define EPI_STRIDE 132
#define NTM (NTOK / GBM)           // 16

template <int HALF_OUT>
__global__ __launch_bounds__(256, 1)
void gemm_f16(const __half* __restrict__ Ah, const __half* __restrict__ Bh,
              const float* __restrict__ bias, const __half* __restrict__ resh,
              void* __restrict__ Cv, int Ntot, int ntiles) {
    extern __shared__ char smem[];
    const uint32_t sb = smem_u32(smem);
    const int tid = threadIdx.x;
    const int wid = tid >> 5;
    const int lane = tid & 31;
    const int warpM = wid >> 1;
    const int warpN = wid & 1;
    const int lrow = lane & 15;
    const int lcol = (lane >> 4) * 16;
    const size_t rowstride = (size_t)GK * 2;

    for (int tile = blockIdx.x; tile < ntiles; tile += gridDim.x) {
        const int tm = tile % NTM;
        const int tn = tile / NTM;
        const char* pAh = (const char*)(Ah + (size_t)tm * GBM * GK);
        const char* pBh = (const char*)(Bh + (size_t)tn * GBN * GK);

        auto issue_loads = [&](int chunk, int s) {
            const uint32_t base = sb + s * STAGE_BYTES;
            const size_t koff = (size_t)chunk * GBK * 2;
#pragma unroll
            for (int sub = 0; sub < 2; sub++) {
                const uint32_t ab = base + sub * A_SUB;
                const uint32_t bb = base + 2 * A_SUB + sub * B_SUB;
                const size_t ko = koff + sub * 128;
#pragma unroll
                for (int j = 0; j < 8; j++) {
                    int u = tid + 256 * j;
                    int row = u >> 3;
                    int c = (u & 7) * 16;
                    uint32_t so = swz128((uint32_t)(row * 128 + c));
                    cp16(ab + so, pAh + (size_t)row * rowstride + ko + c);
                }
#pragma unroll
                for (int j = 0; j < 4; j++) {
                    int u = tid + 256 * j;
                    int row = u >> 3;
                    int c = (u & 7) * 16;
                    uint32_t so = swz128((uint32_t)(row * 128 + c));
                    cp16(bb + so, pBh + (size_t)row * rowstride + ko + c);
                }
            }
            cp_commit();
        };

        float acc[4][8][4];
#pragma unroll
        for (int mt = 0; mt < 4; mt++)
#pragma unroll
            for (int nt = 0; nt < 8; nt++)
#pragma unroll
                for (int e = 0; e < 4; e++) acc[mt][nt][e] = 0.0f;

        issue_loads(0, 0);
        issue_loads(1, 1);

        for (int i = 0; i < NCHUNK; i++) {
            if (i + 1 < NCHUNK) cp_wait1(); else cp_wait0();  // chunk i resident
            __syncthreads();
            const int s = i & 1;
            const uint32_t base = sb + s * STAGE_BYTES;

#pragma unroll
            for (int ks = 0; ks < 8; ks++) {
                const int sub = ks >> 2;
                const int kb = (ks & 3) * 32 + lcol;
                const uint32_t bA = base + sub * A_SUB;
                const uint32_t bB = base + 2 * A_SUB + sub * B_SUB;
                uint32_t aH[4][4], bH[4][4];
#pragma unroll
                for (int mt = 0; mt < 4; mt++) {
                    int row = warpM * 64 + mt * 16 + lrow;
                    ldsm4(aH[mt], bA + swz128((uint32_t)(row * 128 + kb)));
                }
#pragma unroll
                for (int p = 0; p < 4; p++) {
                    int row = warpN * 64 + p * 16 + lrow;
                    ldsm4(bH[p], bB + swz128((uint32_t)(row * 128 + kb)));
                }
#pragma unroll
                for (int mt = 0; mt < 4; mt++) {
#pragma unroll
                    for (int nt = 0; nt < 8; nt++) {
                        const int p = nt >> 1;
                        const int o = nt & 1;
                        mma_f16(acc[mt][nt], aH[mt], bH[p][o], bH[p][o + 2]);
                    }
                }
            }
            __syncthreads();
            if (i + 2 < NCHUNK) issue_loads(i + 2, s);
        }
        __syncthreads();

        // ---- epilogue ----
        float* sf = reinterpret_cast<float*>(smem);
        const int g = lane >> 2;
        const int t2 = (lane & 3) * 2;
#pragma unroll
        for (int mt = 0; mt < 4; mt++) {
#pragma unroll
            for (int nt = 0; nt < 8; nt++) {
                int row = warpM * 64 + mt * 16 + g;
                int col = warpN * 64 + nt * 8 + t2;
                sf[row * EPI_STRIDE + col] = acc[mt][nt][0];
                sf[row * EPI_STRIDE + col + 1] = acc[mt][nt][1];
                sf[(row + 8) * EPI_STRIDE + col] = acc[mt][nt][2];
                sf[(row + 8) * EPI_STRIDE + col + 1] = acc[mt][nt][3];
            }
        }
        __syncthreads();

        const int orow = tid;
        const size_t gbase = (size_t)(tm * GBM + orow) * Ntot + (size_t)tn * GBN;
        const size_t rbase = (size_t)(tm * GBM + orow) * DMODEL + (size_t)tn * GBN;
#pragma unroll
        for (int j = 0; j < 32; j++) {
            int col = j * 4;
            float4 v;
            v.x = sf[orow * EPI_STRIDE + col + 0] + bias[tn * GBN + col + 0];
            v.y = sf[orow * EPI_STRIDE + col + 1] + bias[tn * GBN + col + 1];
            v.z = sf[orow * EPI_STRIDE + col + 2] + bias[tn * GBN + col + 2];
            v.w = sf[orow * EPI_STRIDE + col + 3] + bias[tn * GBN + col + 3];
            if (HALF_OUT) {
                __half2 h0 = __floats2half2_rn(v.x, v.y);
                __half2 h1 = __floats2half2_rn(v.z, v.w);
                uint2 o;
                o.x = *reinterpret_cast<uint32_t*>(&h0);
                o.y = *reinterpret_cast<uint32_t*>(&h1);
                *reinterpret_cast<uint2*>((__half*)Cv + gbase + col) = o;
            } else {
                if (resh != nullptr) {
                    uint2 r2 = *reinterpret_cast<const uint2*>(resh + rbase + col);
                    float2 ra = __half22float2(*reinterpret_cast<__half2*>(&r2.x));
                    float2 rb = __half22float2(*reinterpret_cast<__half2*>(&r2.y));
                    v.x += ra.x; v.y += ra.y; v.z += rb.x; v.w += rb.y;
                }
                *reinterpret_cast<float4*>((float*)Cv + gbase + col) = v;
            }
        }
        __syncthreads();   // sf region reused as stage buffers next tile
    }
}

// ---------------------------------------------------------------------------
// Block-diagonal attention, cp.async double-buffered smem K/V.
// Block = 32 queries x 1 head. Writes only fp16 R1h (context + X residual).
// ---------------------------------------------------------------------------
#define ACH 32
#define KV_BYTES (ACH * DHEAD * 2)
#define ABUF_BYTES (2 * KV_BYTES)
#define ATTN_SMEM (2 * ABUF_BYTES)            // 128 KB

__global__ __launch_bounds__(256)
void attn_kernel(const __half* __restrict__ QKV, const float* __restrict__ X,
                 __half* __restrict__ R1h) {
    extern __shared__ char smem[];
    const uint32_t sb = smem_u32(smem);

    const int tid = threadIdx.x;
    const int lane = tid & 31;
    const int warp = tid >> 5;
    const int q0b = blockIdx.x * 32;
    const int q0 = q0b + warp * 4;
    const int h = blockIdx.y;
    const int hoff = h * DHEAD;

    const int bjmin = g_seg_start[q0b];
    const int bjmax = g_seg_end[q0b + 31];
    const int nch = (bjmax - bjmin + ACH - 1) / ACH;

    int s0[4], s1[4];
    __half2 q2[4][8];
#pragma unroll
    for (int i = 0; i < 4; i++) {
        const int q = q0 + i;
        s0[i] = g_seg_start[q];
        s1[i] = g_seg_end[q];
        const __half2* qrow = (const __half2*)(QKV + (size_t)q * QKV_N + hoff);
#pragma unroll
        for (int d = 0; d < 8; d++) q2[i][d] = qrow[lane + 32 * d];
    }
    const int wjmin = min(min(s0[0], s0[1]), min(s0[2], s0[3]));
    const int wjmax = max(max(s1[0], s1[1]), max(s1[2], s1[3]));

    float m[4] = {-1e30f, -1e30f, -1e30f, -1e30f};
    float l[4] = {0.f, 0.f, 0.f, 0.f};
    float accv[4][16];
#pragma unroll
    for (int i = 0; i < 4; i++)
#pragma unroll
        for (int d = 0; d < 16; d++) accv[i][d] = 0.0f;

    auto load_chunk = [&](int c, int buf) {
        const uint32_t kb = sb + buf * ABUF_BYTES;
        const uint32_t vb = kb + KV_BYTES;
#pragma unroll
        for (int j = 0; j < 8; j++) {
            int e = tid + 256 * j;
            int r = e >> 6;
            int u = (e & 63) * 16;
            int rc = min(c + r, bjmax - 1);
            const char* kg = (const char*)(QKV + (size_t)rc * QKV_N + DMODEL + hoff) + u;
            const char* vg = (const char*)(QKV + (size_t)rc * QKV_N + 2 * DMODEL + hoff) + u;
            cp16(kb + r * 1024 + u, kg);
            cp16(vb + r * 1024 + u, vg);
        }
        cp_commit();
    };

    load_chunk(bjmin, 0);
    if (nch > 1) load_chunk(bjmin + ACH, 1);

    for (int ci = 0; ci < nch; ci++) {
        const int c = bjmin + ci * ACH;
        const int nrows = min(ACH, bjmax - c);
        if (ci + 1 < nch) cp_wait1(); else cp_wait0();
        __syncthreads();

        const int buf = ci & 1;
        const __half* Ks = (const __half*)(smem + buf * ABUF_BYTES);
        const __half* Vs = (const __half*)(smem + buf * ABUF_BYTES + KV_BYTES);

        const int j0 = max(c, wjmin);
        const int j1 = min(c + nrows, wjmax);
        for (int j = j0; j < j1; j++) {
            const __half2* kr = (const __half2*)(Ks + (j - c) * DHEAD);
            float s[4] = {0.f, 0.f, 0.f, 0.f};
#pragma unroll
            for (int d = 0; d < 8; d++) {
                const float2 kf = __half22float2(kr[lane + 32 * d]);
#pragma unroll
                for (int i = 0; i < 4; i++) {
                    const float2 qf = __half22float2(q2[i][d]);
                    s[i] = fmaf(qf.x, kf.x, s[i]);
                    s[i] = fmaf(qf.y, kf.y, s[i]);
                }
            }
#pragma unroll
            for (int off = 16; off > 0; off >>= 1) {
#pragma unroll
                for (int i = 0; i < 4; i++)
                    s[i] += __shfl_xor_sync(0xFFFFFFFFu, s[i], off);
            }

            const __half2* vr = (const __half2*)(Vs + (j - c) * DHEAD);
            float2 vf[8];
#pragma unroll
            for (int d = 0; d < 8; d++) vf[d] = __half22float2(vr[lane + 32 * d]);

#pragma unroll
            for (int i = 0; i < 4; i++) {
                if (j >= s0[i] && j < s1[i]) {
                    const float sc = s[i] * ATTN_SCALE;
                    const float mn = fmaxf(m[i], sc);
                    const float ce = __expf(m[i] - mn);
                    const float p = __expf(sc - mn);
                    l[i] = l[i] * ce + p;
#pragma unroll
                    for (int d = 0; d < 8; d++) {
                        accv[i][2 * d] = fmaf(accv[i][2 * d], ce, p * vf[d].x);
                        accv[i][2 * d + 1] = fmaf(accv[i][2 * d + 1], ce, p * vf[d].y);
                    }
                    m[i] = mn;
                }
            }
        }
        __syncthreads();
        if (ci + 2 < nch) load_chunk(bjmin + (ci + 2) * ACH, buf);
    }

#pragma unroll
    for (int i = 0; i < 4; i++) {
        const int q = q0 + i;
        const float inv = 1.0f / l[i];
        const float2* xr = (const float2*)(X + (size_t)q * DMODEL + hoff);
        __half2* hrow = (__half2*)(R1h + (size_t)q * DMODEL + hoff);
#pragma unroll
        for (int d = 0; d < 8; d++) {
            const float2 x2 = xr[lane + 32 * d];
            hrow[lane + 32 * d] = __floats2half2_rn(
                accv[i][2 * d] * inv + x2.x, accv[i][2 * d + 1] * inv + x2.y);
        }
    }
}

// ---------------------------------------------------------------------------
// kernel_launch
// ---------------------------------------------------------------------------
extern "C" void kernel_launch(void* const* d_in, const int* in_sizes, int n_in,
                              void* d_out, int out_size) {
    const float* X   = (const float*)d_in[0];
    const int*   nr  = (const int*)d_in[1];
    const float* Wq  = (const float*)d_in[2];
    const float* bq  = (const float*)d_in[3];
    const float* Wk  = (const float*)d_in[4];
    const float* bk  = (const float*)d_in[5];
    const float* Wv  = (const float*)d_in[6];
    const float* bv  = (const float*)d_in[7];
    const float* Wfc = (const float*)d_in[8];
    const float* bfc = (const float*)d_in[9];
    float* out = (float*)d_out;

    float *bqkv;
    __half *QKV, *Xh, *R1h, *W;
    cudaGetSymbolAddress((void**)&QKV, g_QKV);
    cudaGetSymbolAddress((void**)&bqkv, g_bqkv);
    cudaGetSymbolAddress((void**)&Xh, g_Xh);
    cudaGetSymbolAddress((void**)&R1h, g_R1h);
    cudaGetSymbolAddress((void**)&W, g_W);

    cudaFuncSetAttribute(gemm_f16<0>, cudaFuncAttributeMaxDynamicSharedMemorySize, GEMM_SMEM);
    cudaFuncSetAttribute(gemm_f16<1>, cudaFuncAttributeMaxDynamicSharedMemorySize, GEMM_SMEM);
    cudaFuncSetAttribute(attn_kernel, cudaFuncAttributeMaxDynamicSharedMemorySize, ATTN_SMEM);

    int nsm = 148;
    cudaDeviceGetAttribute(&nsm, cudaDevAttrMultiProcessorCount, 0);

    const int n4 = (NTOK * DMODEL) / 4;

    // prep
    concat_bias<<<(QKV_N + 255) / 256, 256>>>(bq, bk, bv, bqkv);
    convert_h<<<n4 / 256, 256>>>(X, Xh, n4);
    dim3 tgrid4(DMODEL / 32, DMODEL / 32, 4);
    transpose_conv4<<<tgrid4, 256>>>(Wq, Wk, Wv, Wfc, W);
    build_seg_kernel<<<NTOK / 256, 256>>>(nr, in_sizes[1]);

    // fused QKV projection -> fp16 (persistent)
    const int qkv_tiles = NTM * (QKV_N / GBN);
    gemm_f16<1><<<(qkv_tiles < nsm ? qkv_tiles : nsm), 256, GEMM_SMEM>>>(
        Xh, W, bqkv, nullptr, QKV, QKV_N, qkv_tiles);

    // attention -> R1h (fp16 context + X residual)
    dim3 agrid(NTOK / 32, NHEADS);
    attn_kernel<<<agrid, 256, ATTN_SMEM>>>(QKV, X, R1h);

    // FC: out = R1h + R1h @ Wfc + bfc (persistent)
    const int fc_tiles = NTM * (DMODEL / GBN);
    gemm_f16<0><<<(fc_tiles < nsm ? fc_tiles : nsm), 256, GEMM_SMEM>>>(
        R1h, W + (size_t)3 * DMODEL * DMODEL, bfc, R1h, out, DMODEL, fc_tiles);
}